// round 1
// baseline (speedup 1.0000x reference)
#include <cuda_runtime.h>
#include <math.h>

#define B_   512
#define T_   1005
#define E_   100
#define L_   10
#define N_   20
#define V_   32000
#define NCH  100      // n_full = T/L
#define REST 5        // T % L

// ---- scratch (no allocations allowed) ----
__device__ float g_infos[NCH * B_ * E_];  // [t][b][e]  20.5 MB
__device__ float g_h[B_ * N_ * E_];       // final h
__device__ float g_q[B_ * E_];
__device__ float g_ya[B_ * E_];           // prelu(y)

// ============================================================
// K1: infos[t][b][e] = sum_l f[l][e] * in[b][t*10+l][e]
// ============================================================
__global__ void infos_kernel(const float* __restrict__ in_data,
                             const float* __restrict__ f) {
    int idx = blockIdx.x * 256 + threadIdx.x;
    if (idx >= B_ * NCH * E_) return;
    int e = idx % E_;
    int bn = idx / E_;
    int n = bn % NCH;
    int b = bn / NCH;
    const float* ip = in_data + ((long)b * T_ + n * L_) * E_ + e;
    float acc = 0.f;
#pragma unroll
    for (int l = 0; l < L_; l++) acc += f[l * E_ + e] * ip[(long)l * E_];
    g_infos[(n * B_ + b) * E_ + e] = acc;
}

__global__ void q_kernel(const float* __restrict__ in_data,
                         const float* __restrict__ f) {
    int b = blockIdx.x;
    int e = threadIdx.x;
    if (e >= E_) return;
    const float* ip = in_data + ((long)b * T_ + NCH * L_) * E_ + e;
    float acc = 0.f;
#pragma unroll
    for (int l = 0; l < REST; l++) acc += f[l * E_ + e] * ip[(long)l * E_];
    g_q[b * E_ + e] = acc;
}

// ============================================================
// K2: persistent scan. 128 CTAs x 4 batches, h stays in SMEM.
// ============================================================
#define SU  104   // padded f-stride for transposed U/W (float4-aligned)
#define SHS 101   // padded e-stride for h/w_mem/s (odd -> no 8-row bank alias)
#define NB  4

#define SCAN_SMEM_FLOATS (E_*SU*2 + 80*SHS + N_*SHS + N_*E_ + NB*SHS*2 + 80 + 160 + 80)

__global__ __launch_bounds__(256, 1) void scan_kernel(
    const float* __restrict__ U_w, const float* __restrict__ V_w,
    const float* __restrict__ W_w, const float* __restrict__ w_mem,
    const float* __restrict__ h0,  const float* __restrict__ a_dm_p)
{
    extern __shared__ float sm[];
    float* sUT = sm;                  // [e][f] = U_w[f][e]
    float* sWT = sUT + E_ * SU;       // [e][f] = W_w[f][e]
    float* sH  = sWT + E_ * SU;       // [row=bi*20+n][e], stride SHS
    float* sWm = sH  + 80 * SHS;      // [n][e]
    float* sVw = sWm + N_ * SHS;      // [n][f], stride E_
    float* sS  = sVw + N_ * E_;       // [bi][e]
    float* sSW = sS  + NB * SHS;      // [bi][f]
    float* sG  = sSW + NB * SHS;      // [80]
    float* sGp = sG  + 80;            // [160] partials
    float* sNm = sGp + 160;           // [80]

    int tid = threadIdx.x;
    int b0 = blockIdx.x * NB;
    float adm = *a_dm_p;

    // stage weights (transposed) + w_mem + init h
    for (int i = tid; i < E_ * E_; i += 256) {
        int f_ = i / E_, e_ = i % E_;
        sUT[e_ * SU + f_] = U_w[i];
        sWT[e_ * SU + f_] = W_w[i];
    }
    for (int i = tid; i < N_ * E_; i += 256) {
        int n_ = i / E_, e_ = i % E_;
        sWm[n_ * SHS + e_] = w_mem[i];
    }
    for (int i = tid; i < 80 * E_; i += 256) {
        int row = i / E_, e_ = i % E_;
        sH[row * SHS + e_] = h0[(row % N_) * E_ + e_];
    }
    __syncthreads();
    // Vw[n][f] = sum_e w_mem[n][e] * V_w[f][e]  (one-time, V_w from L2)
    for (int i = tid; i < N_ * E_; i += 256) {
        int n_ = i / E_, f_ = i % E_;
        float acc = 0.f;
        for (int e_ = 0; e_ < E_; e_++) acc += sWm[n_ * SHS + e_] * V_w[f_ * E_ + e_];
        sVw[n_ * E_ + f_] = acc;
    }
    __syncthreads();

    // GEMM mapping: 250 active threads, 8 rows x 4 cols each
    int r = tid / 25, c = tid % 25;
    bool act = tid < 250;
    int rowb = r * 8;
    int colb = c * 4;

    for (int t = 0; t < NCH; t++) {
        // ---- A: load s[bi][e]
        for (int i = tid; i < NB * E_; i += 256) {
            int bi = i / E_, e_ = i % E_;
            sS[bi * SHS + e_] = g_infos[((long)t * B_ + b0 + bi) * E_ + e_];
        }
        __syncthreads();

        // ---- B: sSW[bi][f] = s . W_w[f],  g partials
        for (int i = tid; i < NB * E_; i += 256) {
            int bi = i / E_, f_ = i % E_;
            float acc = 0.f;
#pragma unroll 4
            for (int e_ = 0; e_ < E_; e_++) acc += sS[bi * SHS + e_] * sWT[e_ * SU + f_];
            sSW[bi * SHS + f_] = acc;
        }
        if (tid < 160) {
            int row = tid >> 1, half = tid & 1;
            int bi = row / N_, n_ = row % N_;
            const float* hp = sH + row * SHS;
            const float* wp = sWm + n_ * SHS;
            const float* sp = sS + bi * SHS;
            float acc = 0.f;
            int e0 = half * 50;
#pragma unroll 5
            for (int e_ = e0; e_ < e0 + 50; e_++) acc += (hp[e_] + wp[e_]) * sp[e_];
            sGp[tid] = acc;
        }
        __syncthreads();

        // ---- C: finish g (80 threads) + main GEMM (h @ U_w^T)
        if (tid < 80) {
            float z = sGp[2 * tid] + sGp[2 * tid + 1];
            sG[tid] = 1.f / (1.f + expf(-z));
        }
        float acc[8][4];
        if (act) {
#pragma unroll
            for (int k = 0; k < 8; k++)
#pragma unroll
                for (int j = 0; j < 4; j++) acc[k][j] = 0.f;
#pragma unroll 2
            for (int e_ = 0; e_ < E_; e_++) {
                float4 u4 = *(const float4*)(sUT + e_ * SU + colb);
                float hv[8];
#pragma unroll
                for (int k = 0; k < 8; k++) hv[k] = sH[(rowb + k) * SHS + e_];
#pragma unroll
                for (int k = 0; k < 8; k++) {
                    acc[k][0] += hv[k] * u4.x;
                    acc[k][1] += hv[k] * u4.y;
                    acc[k][2] += hv[k] * u4.z;
                    acc[k][3] += hv[k] * u4.w;
                }
            }
        }
        __syncthreads();

        // ---- D: cand = prelu(acc + Vw + sW); h += g*cand
        if (act) {
#pragma unroll
            for (int k = 0; k < 8; k++) {
                int row = rowb + k;
                int n_ = row % N_;
                int bi = row / N_;
                float g = sG[row];
#pragma unroll
                for (int j = 0; j < 4; j++) {
                    int f_ = colb + j;
                    float cand = acc[k][j] + sVw[n_ * E_ + f_] + sSW[bi * SHS + f_];
                    cand = (cand >= 0.f) ? cand : adm * cand;
                    sH[row * SHS + f_] += g * cand;
                }
            }
        }
        __syncthreads();

        // ---- E: row norms
        if (tid < 160) {
            int row = tid >> 1, half = tid & 1;
            const float* hp = sH + row * SHS + half * 50;
            float a2 = 0.f;
#pragma unroll 5
            for (int e_ = 0; e_ < 50; e_++) { float v = hp[e_]; a2 += v * v; }
            sGp[tid] = a2;
        }
        __syncthreads();
        if (tid < 80) sNm[tid] = 1.f / sqrtf(sGp[2 * tid] + sGp[2 * tid + 1]);
        __syncthreads();

        // ---- F: h /= ||h||
        for (int i = tid; i < 80 * E_; i += 256) {
            int row = i / E_, e_ = i % E_;
            sH[row * SHS + e_] *= sNm[row];
        }
        __syncthreads();
    }

    // write final h
    for (int i = tid; i < 80 * E_; i += 256) {
        int row = i / E_, e_ = i % E_;
        g_h[(long)b0 * N_ * E_ + row * E_ + e_] = sH[row * SHS + e_];
    }
}

// ============================================================
// K3: attention over entities + hidden head, per batch
// ============================================================
__global__ void attn_kernel(const float* __restrict__ H_w,
                            const float* __restrict__ H_b,
                            const float* __restrict__ a_out_p) {
    __shared__ float sh[N_ * E_];
    __shared__ float sq[E_];
    __shared__ float sl[N_];
    __shared__ float sp[N_];
    __shared__ float su[E_];
    int b = blockIdx.x, tid = threadIdx.x;
    for (int i = tid; i < N_ * E_; i += 128) sh[i] = g_h[b * N_ * E_ + i];
    if (tid < E_) sq[tid] = g_q[b * E_ + tid];
    __syncthreads();
    if (tid < N_) {
        float acc = 0.f;
        for (int e = 0; e < E_; e++) acc += sh[tid * E_ + e] * sq[e];
        sl[tid] = acc;
    }
    __syncthreads();
    if (tid == 0) {
        float m = sl[0];
        for (int n = 1; n < N_; n++) m = fmaxf(m, sl[n]);
        float s = 0.f;
        for (int n = 0; n < N_; n++) { float ev = expf(sl[n] - m); sp[n] = ev; s += ev; }
        float inv = 1.f / s;
        for (int n = 0; n < N_; n++) sp[n] *= inv;
    }
    __syncthreads();
    if (tid < E_) {
        float u = 0.f;
        for (int n = 0; n < N_; n++) u += sp[n] * sh[n * E_ + tid];
        su[tid] = u;
    }
    __syncthreads();
    if (tid < E_) {
        int f_ = tid;
        float acc = sq[f_] + H_b[f_];
        for (int e = 0; e < E_; e++) acc += su[e] * H_w[f_ * E_ + e];
        float ao = *a_out_p;
        g_ya[b * E_ + f_] = (acc >= 0.f) ? acc : ao * acc;
    }
}

// ============================================================
// K4: out[b][v] = ya[b] . R_w[v] + R_b[v]   (512 x 32000, K=100)
// ============================================================
#define K4S 68  // padded tile stride (float4-aligned)
__global__ __launch_bounds__(256) void out_kernel(const float* __restrict__ R_w,
                                                  const float* __restrict__ R_b,
                                                  float* __restrict__ out) {
    __shared__ float sA[E_ * K4S];  // [e][bi]
    __shared__ float sB[E_ * K4S];  // [e][vi]
    int tid = threadIdx.x;
    int v0 = blockIdx.x * 64, b0 = blockIdx.y * 64;
    for (int i = tid; i < 64 * E_; i += 256) {
        int bi = i / E_, e = i % E_;
        sA[e * K4S + bi] = g_ya[(b0 + bi) * E_ + e];
    }
    for (int i = tid; i < 64 * E_; i += 256) {
        int vi = i / E_, e = i % E_;
        sB[e * K4S + vi] = R_w[(long)(v0 + vi) * E_ + e];
    }
    __syncthreads();
    int bi4 = (tid >> 4) << 2;
    int vj4 = (tid & 15) << 2;
    float acc[4][4] = {};
#pragma unroll 2
    for (int e = 0; e < E_; e++) {
        float4 a4 = *(const float4*)(sA + e * K4S + bi4);
        float4 r4 = *(const float4*)(sB + e * K4S + vj4);
        float av[4] = {a4.x, a4.y, a4.z, a4.w};
        float rv[4] = {r4.x, r4.y, r4.z, r4.w};
#pragma unroll
        for (int k = 0; k < 4; k++)
#pragma unroll
            for (int j = 0; j < 4; j++) acc[k][j] += av[k] * rv[j];
    }
    float4 rb = *(const float4*)(R_b + v0 + vj4);
    float rbv[4] = {rb.x, rb.y, rb.z, rb.w};
#pragma unroll
    for (int k = 0; k < 4; k++) {
        float4 o;
        o.x = acc[k][0] + rbv[0];
        o.y = acc[k][1] + rbv[1];
        o.z = acc[k][2] + rbv[2];
        o.w = acc[k][3] + rbv[3];
        *(float4*)(out + (long)(b0 + bi4 + k) * V_ + v0 + vj4) = o;
    }
}

// ============================================================
extern "C" void kernel_launch(void* const* d_in, const int* in_sizes, int n_in,
                              void* d_out, int out_size) {
    const float* in_data = (const float*)d_in[0];
    const float* f       = (const float*)d_in[1];
    const float* h0      = (const float*)d_in[2];
    const float* w_mem   = (const float*)d_in[3];
    const float* U_w     = (const float*)d_in[4];
    const float* V_w     = (const float*)d_in[5];
    const float* W_w     = (const float*)d_in[6];
    const float* a_dm    = (const float*)d_in[7];
    const float* H_w     = (const float*)d_in[8];
    const float* H_b     = (const float*)d_in[9];
    const float* R_w     = (const float*)d_in[10];
    const float* R_b     = (const float*)d_in[11];
    const float* a_out   = (const float*)d_in[12];
    float* out = (float*)d_out;

    const int scan_smem = SCAN_SMEM_FLOATS * (int)sizeof(float);  // ~136 KB
    cudaFuncSetAttribute(scan_kernel, cudaFuncAttributeMaxDynamicSharedMemorySize,
                         scan_smem);

    infos_kernel<<<(B_ * NCH * E_ + 255) / 256, 256>>>(in_data, f);
    q_kernel<<<B_, 128>>>(in_data, f);
    scan_kernel<<<B_ / NB, 256, scan_smem>>>(U_w, V_w, W_w, w_mem, h0, a_dm);
    attn_kernel<<<B_, 128>>>(H_w, H_b, a_out);
    dim3 g4(V_ / 64, B_ / 64);
    out_kernel<<<g4, 256>>>(R_w, R_b, out);
}

// round 2
// speedup vs baseline: 1.0153x; 1.0153x over previous
#include <cuda_runtime.h>
#include <math.h>

#define B_   512
#define T_   1005
#define E_   100
#define L_   10
#define N_   20
#define V_   32000
#define NCH  100      // n_full = T/L
#define REST 5        // T % L

// ---- scratch (no allocations allowed) ----
__device__ float g_infos[NCH * B_ * E_];  // [t][b][e]
__device__ float g_h[B_ * N_ * E_];       // final h
__device__ float g_q[B_ * E_];
__device__ float g_ya[B_ * E_];           // prelu(y)

// ---- packed fp32x2 helpers (sm_103a FFMA2) ----
__device__ __forceinline__ unsigned long long lds2(const float* p) {
    // caller guarantees 8B alignment
    return *reinterpret_cast<const unsigned long long*>(p);
}
__device__ __forceinline__ void ffma2(unsigned long long& d,
                                      unsigned long long a,
                                      unsigned long long b) {
    asm("fma.rn.f32x2 %0, %1, %2, %0;" : "+l"(d) : "l"(a), "l"(b));
}
__device__ __forceinline__ float hadd2(unsigned long long v) {
    float lo, hi;
    asm("mov.b64 {%0, %1}, %2;" : "=f"(lo), "=f"(hi) : "l"(v));
    return lo + hi;
}

// ============================================================
// K1: infos[t][b][e] = sum_l f[l][e] * in[b][t*10+l][e]
// ============================================================
__global__ void infos_kernel(const float* __restrict__ in_data,
                             const float* __restrict__ f) {
    int idx = blockIdx.x * 256 + threadIdx.x;
    if (idx >= B_ * NCH * E_) return;
    int e = idx % E_;
    int bn = idx / E_;
    int n = bn % NCH;
    int b = bn / NCH;
    const float* ip = in_data + ((long)b * T_ + n * L_) * E_ + e;
    float acc = 0.f;
#pragma unroll
    for (int l = 0; l < L_; l++) acc += f[l * E_ + e] * ip[(long)l * E_];
    g_infos[(n * B_ + b) * E_ + e] = acc;
}

__global__ void q_kernel(const float* __restrict__ in_data,
                         const float* __restrict__ f) {
    int b = blockIdx.x;
    int e = threadIdx.x;
    if (e >= E_) return;
    const float* ip = in_data + ((long)b * T_ + NCH * L_) * E_ + e;
    float acc = 0.f;
#pragma unroll
    for (int l = 0; l < REST; l++) acc += f[l * E_ + e] * ip[(long)l * E_];
    g_q[b * E_ + e] = acc;
}

// ============================================================
// K2: persistent scan. 128 CTAs x 4 batches, h resident in SMEM.
//     GEMMs run on packed f32x2 FFMA (K-dim vectorized).
// ============================================================
#define SHS 102   // even padded e-stride for h/w_mem/s (8B-aligned pairs)
#define NB  4
#define NTH 512
#define NP  50    // E_/2 pair count

// floats: sU2 + sW2 + sH + sWm + sVw + sS + sSW + sG + sGp + sNm
#define SCAN_SMEM_FLOATS (10000 + 10000 + 80*SHS + N_*SHS + N_*E_ + NB*SHS + NB*SHS + 80 + 160 + 80)

__global__ __launch_bounds__(NTH, 1) void scan_kernel(
    const float* __restrict__ U_w, const float* __restrict__ V_w,
    const float* __restrict__ W_w, const float* __restrict__ w_mem,
    const float* __restrict__ h0,  const float* __restrict__ a_dm_p)
{
    extern __shared__ float sm[];
    float* sU2 = sm;                  // [p][f] float2 pairs of U_w (e=2p,2p+1)
    float* sW2 = sU2 + 10000;         // [p][f] float2 pairs of W_w
    float* sH  = sW2 + 10000;         // [row=bi*20+n][e], stride SHS
    float* sWm = sH  + 80 * SHS;      // [n][e], stride SHS
    float* sVw = sWm + N_ * SHS;      // [n][f], stride E_
    float* sS  = sVw + N_ * E_;       // [bi][e], stride SHS
    float* sSW = sS  + NB * SHS;      // [bi][f], stride SHS
    float* sG  = sSW + NB * SHS;      // [80]
    float* sGp = sG  + 80;            // [160] partials
    float* sNm = sGp + 160;           // [80]

    int tid = threadIdx.x;
    int b0 = blockIdx.x * NB;
    float adm = *a_dm_p;

    // ---- stage weights as (e,e+1) pair-major, w_mem, init h ----
    for (int i = tid; i < NP * E_; i += NTH) {
        int p = i / E_, f_ = i % E_;
        sU2[i * 2]     = U_w[f_ * E_ + 2 * p];
        sU2[i * 2 + 1] = U_w[f_ * E_ + 2 * p + 1];
        sW2[i * 2]     = W_w[f_ * E_ + 2 * p];
        sW2[i * 2 + 1] = W_w[f_ * E_ + 2 * p + 1];
    }
    for (int i = tid; i < N_ * E_; i += NTH) {
        int n_ = i / E_, e_ = i % E_;
        sWm[n_ * SHS + e_] = w_mem[i];
    }
    for (int i = tid; i < 80 * E_; i += NTH) {
        int row = i / E_, e_ = i % E_;
        sH[row * SHS + e_] = h0[(row % N_) * E_ + e_];
    }
    __syncthreads();
    // Vw[n][f] = sum_e w_mem[n][e] * V_w[f][e]  (one-time)
    for (int i = tid; i < N_ * E_; i += NTH) {
        int n_ = i / E_, f_ = i % E_;
        float acc = 0.f;
        for (int e_ = 0; e_ < E_; e_++) acc += sWm[n_ * SHS + e_] * V_w[f_ * E_ + e_];
        sVw[n_ * E_ + f_] = acc;
    }
    __syncthreads();

    // GEMM mapping: 500 active threads, each 4 rows x 4 strided cols
    int r = tid / 25, c = tid % 25;   // r in [0,20), c in [0,25)
    bool act = tid < 500;
    int rowb = r * 4;                 // cols are {c, c+25, c+50, c+75}

    for (int t = 0; t < NCH; t++) {
        // ---- A: load s[bi][e]
        for (int i = tid; i < NB * E_; i += NTH) {
            int bi = i / E_, e_ = i % E_;
            sS[bi * SHS + e_] = g_infos[((long)t * B_ + b0 + bi) * E_ + e_];
        }
        __syncthreads();

        // ---- B: sSW[bi][f] = s . W_w[f]  (FFMA2)  + g partials
        if (tid < NB * E_) {
            int bi = tid / E_, f_ = tid % E_;
            unsigned long long a2 = 0ull;
#pragma unroll 2
            for (int p = 0; p < NP; p++) {
                unsigned long long s2 = lds2(sS + bi * SHS + 2 * p);
                unsigned long long w2 = lds2(sW2 + (p * E_ + f_) * 2);
                ffma2(a2, s2, w2);
            }
            sSW[bi * SHS + f_] = hadd2(a2);
        }
        if (tid < 160) {
            int row = tid >> 1, half = tid & 1;
            int bi = row / N_, n_ = row % N_;
            const float* hp = sH + row * SHS;
            const float* wp = sWm + n_ * SHS;
            const float* sp = sS + bi * SHS;
            float acc = 0.f;
            int e0 = half * 50;
#pragma unroll 5
            for (int e_ = e0; e_ < e0 + 50; e_++) acc += (hp[e_] + wp[e_]) * sp[e_];
            sGp[tid] = acc;
        }
        __syncthreads();

        // ---- C: sigmoid (80 thr) + main GEMM h @ U_w^T (FFMA2)
        if (tid < 80) {
            float z = sGp[2 * tid] + sGp[2 * tid + 1];
            sG[tid] = 1.f / (1.f + expf(-z));
        }
        unsigned long long acc2[4][4];
        if (act) {
#pragma unroll
            for (int k = 0; k < 4; k++)
#pragma unroll
                for (int j = 0; j < 4; j++) acc2[k][j] = 0ull;
#pragma unroll 2
            for (int p = 0; p < NP; p++) {
                unsigned long long u2[4], h2[4];
#pragma unroll
                for (int j = 0; j < 4; j++)
                    u2[j] = lds2(sU2 + (p * E_ + c + 25 * j) * 2);
#pragma unroll
                for (int k = 0; k < 4; k++)
                    h2[k] = lds2(sH + (rowb + k) * SHS + 2 * p);
#pragma unroll
                for (int k = 0; k < 4; k++)
#pragma unroll
                    for (int j = 0; j < 4; j++) ffma2(acc2[k][j], h2[k], u2[j]);
            }
        }
        __syncthreads();

        // ---- D: cand = prelu(acc + Vw + sW); h += g*cand
        if (act) {
#pragma unroll
            for (int k = 0; k < 4; k++) {
                int row = rowb + k;
                int n_ = row % N_;
                int bi = row / N_;
                float g = sG[row];
#pragma unroll
                for (int j = 0; j < 4; j++) {
                    int f_ = c + 25 * j;
                    float cand = hadd2(acc2[k][j]) + sVw[n_ * E_ + f_] + sSW[bi * SHS + f_];
                    cand = (cand >= 0.f) ? cand : adm * cand;
                    sH[row * SHS + f_] += g * cand;
                }
            }
        }
        __syncthreads();

        // ---- E: row sumsq partials
        if (tid < 160) {
            int row = tid >> 1, half = tid & 1;
            const float* hp = sH + row * SHS + half * 50;
            float a2 = 0.f;
#pragma unroll 5
            for (int e_ = 0; e_ < 50; e_++) { float v = hp[e_]; a2 += v * v; }
            sGp[tid] = a2;
        }
        __syncthreads();
        if (tid < 80) sNm[tid] = 1.f / sqrtf(sGp[2 * tid] + sGp[2 * tid + 1]);
        __syncthreads();

        // ---- F: h /= ||h||
        for (int i = tid; i < 80 * E_; i += NTH) {
            int row = i / E_, e_ = i % E_;
            sH[row * SHS + e_] *= sNm[row];
        }
        __syncthreads();
    }

    // write final h
    for (int i = tid; i < 80 * E_; i += NTH) {
        int row = i / E_, e_ = i % E_;
        g_h[(long)b0 * N_ * E_ + row * E_ + e_] = sH[row * SHS + e_];
    }
}

// ============================================================
// K3: attention over entities + hidden head, per batch
// ============================================================
__global__ void attn_kernel(const float* __restrict__ H_w,
                            const float* __restrict__ H_b,
                            const float* __restrict__ a_out_p) {
    __shared__ float sh[N_ * E_];
    __shared__ float sq[E_];
    __shared__ float sl[N_];
    __shared__ float sp[N_];
    __shared__ float su[E_];
    int b = blockIdx.x, tid = threadIdx.x;
    for (int i = tid; i < N_ * E_; i += 128) sh[i] = g_h[b * N_ * E_ + i];
    if (tid < E_) sq[tid] = g_q[b * E_ + tid];
    __syncthreads();
    if (tid < N_) {
        float acc = 0.f;
        for (int e = 0; e < E_; e++) acc += sh[tid * E_ + e] * sq[e];
        sl[tid] = acc;
    }
    __syncthreads();
    if (tid == 0) {
        float m = sl[0];
        for (int n = 1; n < N_; n++) m = fmaxf(m, sl[n]);
        float s = 0.f;
        for (int n = 0; n < N_; n++) { float ev = expf(sl[n] - m); sp[n] = ev; s += ev; }
        float inv = 1.f / s;
        for (int n = 0; n < N_; n++) sp[n] *= inv;
    }
    __syncthreads();
    if (tid < E_) {
        float u = 0.f;
        for (int n = 0; n < N_; n++) u += sp[n] * sh[n * E_ + tid];
        su[tid] = u;
    }
    __syncthreads();
    if (tid < E_) {
        int f_ = tid;
        float acc = sq[f_] + H_b[f_];
        for (int e = 0; e < E_; e++) acc += su[e] * H_w[f_ * E_ + e];
        float ao = *a_out_p;
        g_ya[b * E_ + f_] = (acc >= 0.f) ? acc : ao * acc;
    }
}

// ============================================================
// K4: out[b][v] = ya[b] . R_w[v] + R_b[v]  (512 x 32000, K=100)
//     FFMA2, K-pair staged tiles.
// ============================================================
#define K4_SMEM_FLOATS (64*NP*2 * 2)
__global__ __launch_bounds__(256) void out_kernel(const float* __restrict__ R_w,
                                                  const float* __restrict__ R_b,
                                                  float* __restrict__ out) {
    extern __shared__ float osm[];
    float* sA2 = osm;              // [p][bi] float2 pairs
    float* sB2 = osm + 64 * NP * 2;  // [p][vi] float2 pairs
    int tid = threadIdx.x;
    int v0 = blockIdx.x * 64, b0 = blockIdx.y * 64;
    for (int i = tid; i < 64 * NP; i += 256) {
        int bi = i / NP, p = i % NP;
        const float* src = g_ya + (long)(b0 + bi) * E_ + 2 * p;
        sA2[(p * 64 + bi) * 2]     = src[0];
        sA2[(p * 64 + bi) * 2 + 1] = src[1];
    }
    for (int i = tid; i < 64 * NP; i += 256) {
        int vi = i / NP, p = i % NP;
        const float* src = R_w + (long)(v0 + vi) * E_ + 2 * p;
        sB2[(p * 64 + vi) * 2]     = src[0];
        sB2[(p * 64 + vi) * 2 + 1] = src[1];
    }
    __syncthreads();
    int bi4 = (tid >> 4) << 2;    // rows bi4..bi4+3
    int vj  = tid & 15;           // cols {vj, vj+16, vj+32, vj+48}
    unsigned long long acc2[4][4];
#pragma unroll
    for (int k = 0; k < 4; k++)
#pragma unroll
        for (int j = 0; j < 4; j++) acc2[k][j] = 0ull;
#pragma unroll 2
    for (int p = 0; p < NP; p++) {
        unsigned long long a2[4], b2[4];
#pragma unroll
        for (int k = 0; k < 4; k++) a2[k] = lds2(sA2 + (p * 64 + bi4 + k) * 2);
#pragma unroll
        for (int j = 0; j < 4; j++) b2[j] = lds2(sB2 + (p * 64 + vj + 16 * j) * 2);
#pragma unroll
        for (int k = 0; k < 4; k++)
#pragma unroll
            for (int j = 0; j < 4; j++) ffma2(acc2[k][j], a2[k], b2[j]);
    }
    float rb[4];
#pragma unroll
    for (int j = 0; j < 4; j++) rb[j] = R_b[v0 + vj + 16 * j];
#pragma unroll
    for (int k = 0; k < 4; k++) {
#pragma unroll
        for (int j = 0; j < 4; j++) {
            out[(long)(b0 + bi4 + k) * V_ + v0 + vj + 16 * j] = hadd2(acc2[k][j]) + rb[j];
        }
    }
}

// ============================================================
extern "C" void kernel_launch(void* const* d_in, const int* in_sizes, int n_in,
                              void* d_out, int out_size) {
    const float* in_data = (const float*)d_in[0];
    const float* f       = (const float*)d_in[1];
    const float* h0      = (const float*)d_in[2];
    const float* w_mem   = (const float*)d_in[3];
    const float* U_w     = (const float*)d_in[4];
    const float* V_w     = (const float*)d_in[5];
    const float* W_w     = (const float*)d_in[6];
    const float* a_dm    = (const float*)d_in[7];
    const float* H_w     = (const float*)d_in[8];
    const float* H_b     = (const float*)d_in[9];
    const float* R_w     = (const float*)d_in[10];
    const float* R_b     = (const float*)d_in[11];
    const float* a_out   = (const float*)d_in[12];
    float* out = (float*)d_out;

    const int scan_smem = SCAN_SMEM_FLOATS * (int)sizeof(float);  // ~130 KB
    cudaFuncSetAttribute(scan_kernel, cudaFuncAttributeMaxDynamicSharedMemorySize,
                         scan_smem);
    const int k4_smem = K4_SMEM_FLOATS * (int)sizeof(float);      // 51200 B
    cudaFuncSetAttribute(out_kernel, cudaFuncAttributeMaxDynamicSharedMemorySize,
                         k4_smem);

    infos_kernel<<<(B_ * NCH * E_ + 255) / 256, 256>>>(in_data, f);
    q_kernel<<<B_, 128>>>(in_data, f);
    scan_kernel<<<B_ / NB, NTH, scan_smem>>>(U_w, V_w, W_w, w_mem, h0, a_dm);
    attn_kernel<<<B_, 128>>>(H_w, H_b, a_out);
    dim3 g4(V_ / 64, B_ / 64);
    out_kernel<<<g4, 256, k4_smem>>>(R_w, R_b, out);
}

// round 4
// speedup vs baseline: 1.8101x; 1.7829x over previous
#include <cuda_runtime.h>
#include <cuda_bf16.h>
#include <math.h>
#include <stdint.h>

#define B_   512
#define T_   1005
#define E_   100
#define L_   10
#define N_   20
#define V_   32000
#define NCH  100      // n_full = T/L
#define REST 5        // T % L

// ---- scratch (no allocations allowed) ----
__device__ float g_infos[NCH * B_ * E_];  // [t][b][e]
__device__ float g_h[B_ * N_ * E_];       // final h
__device__ float g_q[B_ * E_];
__device__ float g_ya[B_ * E_];           // prelu(y)

// ---- packed fp32x2 helpers (out_kernel) ----
__device__ __forceinline__ unsigned long long lds2(const float* p) {
    return *reinterpret_cast<const unsigned long long*>(p);
}
__device__ __forceinline__ void ffma2(unsigned long long& d,
                                      unsigned long long a,
                                      unsigned long long b) {
    asm("fma.rn.f32x2 %0, %1, %2, %0;" : "+l"(d) : "l"(a), "l"(b));
}
__device__ __forceinline__ float hadd2(unsigned long long v) {
    float lo, hi;
    asm("mov.b64 {%0, %1}, %2;" : "=f"(lo), "=f"(hi) : "l"(v));
    return lo + hi;
}

// ---- warp MMA helpers (portable PTX, sm_80+) ----
__device__ __forceinline__ uint32_t smem_u32(const void* p) {
    uint32_t a;
    asm("{ .reg .u64 t; cvta.to.shared.u64 t, %1; cvt.u32.u64 %0, t; }"
        : "=r"(a) : "l"(p));
    return a;
}
__device__ __forceinline__ void ldsm4(uint32_t* r, uint32_t a) {
    asm volatile("ldmatrix.sync.aligned.m8n8.x4.shared.b16 {%0,%1,%2,%3}, [%4];"
        : "=r"(r[0]), "=r"(r[1]), "=r"(r[2]), "=r"(r[3]) : "r"(a));
}
__device__ __forceinline__ void ldsm2(uint32_t* r, uint32_t a) {
    asm volatile("ldmatrix.sync.aligned.m8n8.x2.shared.b16 {%0,%1}, [%2];"
        : "=r"(r[0]), "=r"(r[1]) : "r"(a));
}
__device__ __forceinline__ void mma16816(float* c, const uint32_t* a, const uint32_t* b) {
    asm volatile(
        "mma.sync.aligned.m16n8k16.row.col.f32.bf16.bf16.f32 "
        "{%0,%1,%2,%3}, {%4,%5,%6,%7}, {%8,%9}, {%0,%1,%2,%3};"
        : "+f"(c[0]), "+f"(c[1]), "+f"(c[2]), "+f"(c[3])
        : "r"(a[0]), "r"(a[1]), "r"(a[2]), "r"(a[3]), "r"(b[0]), "r"(b[1]));
}
__device__ __forceinline__ uint32_t pack_bf2(float f0, float f1) {
    __nv_bfloat16 b0 = __float2bfloat16(f0);
    __nv_bfloat16 b1 = __float2bfloat16(f1);
    return (uint32_t)__bfloat16_as_ushort(b0) | ((uint32_t)__bfloat16_as_ushort(b1) << 16);
}

// ============================================================
// K1: infos[t][b][e] = sum_l f[l][e] * in[b][t*10+l][e]
// ============================================================
__global__ void infos_kernel(const float* __restrict__ in_data,
                             const float* __restrict__ f) {
    int idx = blockIdx.x * 256 + threadIdx.x;
    if (idx >= B_ * NCH * E_) return;
    int e = idx % E_;
    int bn = idx / E_;
    int n = bn % NCH;
    int b = bn / NCH;
    const float* ip = in_data + ((long)b * T_ + n * L_) * E_ + e;
    float acc = 0.f;
#pragma unroll
    for (int l = 0; l < L_; l++) acc += f[l * E_ + e] * ip[(long)l * E_];
    g_infos[(n * B_ + b) * E_ + e] = acc;
}

__global__ void q_kernel(const float* __restrict__ in_data,
                         const float* __restrict__ f) {
    int b = blockIdx.x;
    int e = threadIdx.x;
    if (e >= E_) return;
    const float* ip = in_data + ((long)b * T_ + NCH * L_) * E_ + e;
    float acc = 0.f;
#pragma unroll
    for (int l = 0; l < REST; l++) acc += f[l * E_ + e] * ip[(long)l * E_];
    g_q[b * E_ + e] = acc;
}

// ============================================================
// K2: persistent scan on warp-level bf16 MMA (HMMA), bf16x3.
//     128 CTAs x 4 batches; h fp32 in SMEM (pre-norm, deferred inv).
// ============================================================
#define NB   4
#define NTH  512
#define BST  240      // byte stride of bf16 tile rows (15*16B -> LDSM conflict-free)
#define HST  108      // float stride of sH rows

// byte offsets in dynamic smem (all 16B aligned)
#define OFF_AHI 0                         // 80*240  = 19200
#define OFF_ALO 19200                     // 19200
#define OFF_BHI 38400                     // 112*240 = 26880
#define OFF_BLO 65280                     // 26880
#define OFF_H   92160                     // 80*108*4 = 34560
#define OFF_W   126720                    // 100*100*4 = 40000
#define OFF_WM  166720                    // 20*104*4 = 8320
#define OFF_VW  175040                    // 20*104*4 = 8320
#define OFF_S   183360                    // 2*4*104*4 = 3328
#define OFF_SSW 186688                    // 4*104*4 = 1664
#define OFF_G   188352                    // 80*4
#define OFF_GP  188672                    // 160*4
#define OFF_INV 189312                    // 80*4
#define SCAN_SMEM 189632

__device__ __forceinline__ uint32_t a_frag_addr(uint32_t base, int m0, int k, int lane) {
    int grp = lane >> 3, lr = lane & 7;
    int row = m0 + lr + ((grp & 1) << 3);
    int kb = k * 32 + ((grp >> 1) << 4);
    return base + row * BST + kb;
}
__device__ __forceinline__ uint32_t b_frag_addr(uint32_t base, int n0, int k, int lane) {
    int l = lane & 15;
    int row = n0 + (l & 7);
    int kb = k * 32 + ((l >> 3) << 4);
    return base + row * BST + kb;
}

__global__ __launch_bounds__(NTH, 1) void scan_mma_kernel(
    const float* __restrict__ U_w, const float* __restrict__ V_w,
    const float* __restrict__ W_w, const float* __restrict__ w_mem,
    const float* __restrict__ h0,  const float* __restrict__ a_dm_p)
{
    extern __shared__ char smc[];
    float* sH  = (float*)(smc + OFF_H);
    float* sW  = (float*)(smc + OFF_W);
    float* sWm = (float*)(smc + OFF_WM);
    float* sVw = (float*)(smc + OFF_VW);
    float* sS  = (float*)(smc + OFF_S);
    float* sSW = (float*)(smc + OFF_SSW);
    float* sG  = (float*)(smc + OFF_G);
    float* sGp = (float*)(smc + OFF_GP);
    float* sInv= (float*)(smc + OFF_INV);

    const int tid = threadIdx.x;
    const int w = tid >> 5;
    const int lane = tid & 31;
    const int b0g = blockIdx.x * NB;
    const float adm = *a_dm_p;
    const uint32_t smb = smem_u32(smc);

    // ---- zero bf16 tiles (pads must stay zero) ----
    for (int i = tid; i < OFF_H / 4; i += NTH) ((uint32_t*)smc)[i] = 0;
    __syncthreads();

    // ---- stage B = U (bf16 hi/lo), W, w_mem, h init, sGp init ----
    for (int i = tid; i < E_ * 50; i += NTH) {
        int f_ = i / 50, p = i % 50;
        float2 uv = *(const float2*)(U_w + f_ * E_ + 2 * p);
        __nv_bfloat16 bh0 = __float2bfloat16(uv.x);
        __nv_bfloat16 bh1 = __float2bfloat16(uv.y);
        uint32_t hi = (uint32_t)__bfloat16_as_ushort(bh0) |
                      ((uint32_t)__bfloat16_as_ushort(bh1) << 16);
        uint32_t lo = pack_bf2(uv.x - __bfloat162float(bh0),
                               uv.y - __bfloat162float(bh1));
        *(uint32_t*)(smc + OFF_BHI + f_ * BST + p * 4) = hi;
        *(uint32_t*)(smc + OFF_BLO + f_ * BST + p * 4) = lo;
    }
    for (int i = tid; i < E_ * E_; i += NTH) sW[i] = W_w[i];
    for (int i = tid; i < N_ * E_; i += NTH) {
        int n_ = i / E_, e_ = i % E_;
        sWm[n_ * 104 + e_] = w_mem[i];
    }
    for (int i = tid; i < 80 * E_; i += NTH) {
        int row = i / E_, e_ = i % E_;
        sH[row * HST + e_] = h0[(row % N_) * E_ + e_];
    }
    if (tid < 80) { sGp[2 * tid] = 1.f; sGp[2 * tid + 1] = 0.f; }
    // preload s_0
    if (tid < NB * E_) {
        int bi = tid / E_, e_ = tid % E_;
        sS[bi * 104 + e_] = g_infos[((long)0 * B_ + b0g + bi) * E_ + e_];
    }
    __syncthreads();
    // Vw[n][f] = w_mem[n] . V_w[f]  (one-time, V_w from L2)
    for (int i = tid; i < N_ * E_; i += NTH) {
        int n_ = i / E_, f_ = i % E_;
        float acc = 0.f;
        for (int e_ = 0; e_ < E_; e_++) acc += sWm[n_ * 104 + e_] * V_w[f_ * E_ + e_];
        sVw[n_ * 104 + f_] = acc;
    }
    __syncthreads();

    const int stripe = w >> 1, nh = w & 1;
    const int m0 = stripe * 16;
    const int qr = lane >> 2, qc = lane & 3;

    for (int t = 0; t < NCH; t++) {
        const float* sScur = sS + (t & 1) * NB * 104;

        // ---- P1: convert h_norm -> A hi/lo tiles; prefetch s_{t+1}
        for (int i = tid; i < 4000; i += NTH) {
            int row = i / 50, p = i % 50;
            float inv = rsqrtf(sGp[2 * row] + sGp[2 * row + 1]);
            float2 hv = *(float2*)(sH + row * HST + 2 * p);
            float f0 = hv.x * inv, f1 = hv.y * inv;
            __nv_bfloat16 bh0 = __float2bfloat16(f0);
            __nv_bfloat16 bh1 = __float2bfloat16(f1);
            uint32_t hi = (uint32_t)__bfloat16_as_ushort(bh0) |
                          ((uint32_t)__bfloat16_as_ushort(bh1) << 16);
            uint32_t lo = pack_bf2(f0 - __bfloat162float(bh0),
                                   f1 - __bfloat162float(bh1));
            *(uint32_t*)(smc + OFF_AHI + row * BST + p * 4) = hi;
            *(uint32_t*)(smc + OFF_ALO + row * BST + p * 4) = lo;
        }
        if (tid >= 64 && tid < 64 + NB * E_ && t + 1 < NCH) {
            int i = tid - 64;
            int bi = i / E_, e_ = i % E_;
            sS[((t + 1) & 1) * NB * 104 + bi * 104 + e_] =
                g_infos[((long)(t + 1) * B_ + b0g + bi) * E_ + e_];
        }
        __syncthreads();

        // ---- P2: MMA (warps 0-9)  |  gate + s@W^T (warps 10-15)
        float acc[7][4];
        if (w < 10) {
#pragma unroll
            for (int j = 0; j < 7; j++)
#pragma unroll
                for (int q = 0; q < 4; q++) acc[j][q] = 0.f;
            for (int k = 0; k < 7; k++) {
                uint32_t ah[4], al[4];
                uint32_t aa = a_frag_addr(smb + OFF_AHI, m0, k, lane);
                ldsm4(ah, aa);
                ldsm4(al, aa + (OFF_ALO - OFF_AHI));
#pragma unroll
                for (int j = 0; j < 7; j++) {
                    int n0 = (nh * 7 + j) * 8;
                    uint32_t bh[2], bl[2];
                    uint32_t ba = b_frag_addr(smb + OFF_BHI, n0, k, lane);
                    ldsm2(bh, ba);
                    ldsm2(bl, ba + (OFF_BLO - OFF_BHI));
                    mma16816(acc[j], ah, bh);
                    mma16816(acc[j], al, bh);
                    mma16816(acc[j], ah, bl);
                }
            }
        } else {
            int i = tid - 320;
            if (i < 100) {
                // sSW[bi][f=i] = s[bi] . W[f]
                int f_ = i;
                float a0 = 0.f, a1 = 0.f, a2 = 0.f, a3 = 0.f;
                const float* wp = sW + f_ * E_;
                for (int e4 = 0; e4 < 25; e4++) {
                    float4 wv = *(const float4*)(wp + e4 * 4);
                    float4 s0 = *(const float4*)(sScur + 0 * 104 + e4 * 4);
                    float4 s1 = *(const float4*)(sScur + 1 * 104 + e4 * 4);
                    float4 s2 = *(const float4*)(sScur + 2 * 104 + e4 * 4);
                    float4 s3 = *(const float4*)(sScur + 3 * 104 + e4 * 4);
                    a0 += wv.x * s0.x + wv.y * s0.y + wv.z * s0.z + wv.w * s0.w;
                    a1 += wv.x * s1.x + wv.y * s1.y + wv.z * s1.z + wv.w * s1.w;
                    a2 += wv.x * s2.x + wv.y * s2.y + wv.z * s2.z + wv.w * s2.w;
                    a3 += wv.x * s3.x + wv.y * s3.y + wv.z * s3.z + wv.w * s3.w;
                }
                sSW[0 * 104 + f_] = a0;
                sSW[1 * 104 + f_] = a1;
                sSW[2 * 104 + f_] = a2;
                sSW[3 * 104 + f_] = a3;
            } else if (i < 180) {
                // gate: z[row] = inv*(h.s) + wm.s ; also publish sInv[row]
                int row = i - 100;
                int bi = row / N_, ne = row % N_;
                const float* hp = sH + row * HST;
                const float* wp = sWm + ne * 104;
                const float* sp = sScur + bi * 104;
                float hs = 0.f, ws = 0.f;
                for (int e4 = 0; e4 < 25; e4++) {
                    float4 hv = *(const float4*)(hp + e4 * 4);
                    float4 wv = *(const float4*)(wp + e4 * 4);
                    float4 sv = *(const float4*)(sp + e4 * 4);
                    hs += hv.x * sv.x + hv.y * sv.y + hv.z * sv.z + hv.w * sv.w;
                    ws += wv.x * sv.x + wv.y * sv.y + wv.z * sv.z + wv.w * sv.w;
                }
                float inv = rsqrtf(sGp[2 * row] + sGp[2 * row + 1]);
                sInv[row] = inv;
                sG[row] = 1.f / (1.f + expf(-(inv * hs + ws)));
            }
        }
        __syncthreads();

        // ---- P3: epilogue (warps 0-9): h <- h*inv + g*prelu(cand)
        if (w < 10) {
            int r0 = m0 + qr, r1 = r0 + 8;
            float inv0 = sInv[r0], inv1 = sInv[r1];
            float g0 = sG[r0], g1 = sG[r1];
            int bi0 = r0 / N_, ne0 = r0 % N_;
            int bi1 = r1 / N_, ne1 = r1 % N_;
            float ssq0 = 0.f, ssq1 = 0.f;
#pragma unroll
            for (int j = 0; j < 7; j++) {
                int f0 = (nh * 7 + j) * 8 + 2 * qc;
#pragma unroll
                for (int u = 0; u < 2; u++) {
                    int f_ = f0 + u;
                    if (f_ < 100) {
                        {
                            float cand = acc[j][u] + sVw[ne0 * 104 + f_] + sSW[bi0 * 104 + f_];
                            cand = (cand >= 0.f) ? cand : adm * cand;
                            float hn = sH[r0 * HST + f_] * inv0 + g0 * cand;
                            sH[r0 * HST + f_] = hn;
                            ssq0 += hn * hn;
                        }
                        {
                            float cand = acc[j][2 + u] + sVw[ne1 * 104 + f_] + sSW[bi1 * 104 + f_];
                            cand = (cand >= 0.f) ? cand : adm * cand;
                            float hn = sH[r1 * HST + f_] * inv1 + g1 * cand;
                            sH[r1 * HST + f_] = hn;
                            ssq1 += hn * hn;
                        }
                    }
                }
            }
            ssq0 += __shfl_xor_sync(0xffffffffu, ssq0, 1);
            ssq0 += __shfl_xor_sync(0xffffffffu, ssq0, 2);
            ssq1 += __shfl_xor_sync(0xffffffffu, ssq1, 1);
            ssq1 += __shfl_xor_sync(0xffffffffu, ssq1, 2);
            if (qc == 0) {
                sGp[2 * r0 + nh] = ssq0;
                sGp[2 * r1 + nh] = ssq1;
            }
        }
        __syncthreads();
    }

    // ---- final normalize + write h ----
    for (int i = tid; i < 80 * E_; i += NTH) {
        int row = i / E_, e_ = i % E_;
        float inv = rsqrtf(sGp[2 * row] + sGp[2 * row + 1]);
        g_h[(long)(b0g + row / N_) * N_ * E_ + (row % N_) * E_ + e_] =
            sH[row * HST + e_] * inv;
    }
}

// ============================================================
// K3: attention over entities + hidden head, per batch
// ============================================================
__global__ void attn_kernel(const float* __restrict__ H_w,
                            const float* __restrict__ H_b,
                            const float* __restrict__ a_out_p) {
    __shared__ float sh[N_ * E_];
    __shared__ float sq[E_];
    __shared__ float sl[N_];
    __shared__ float sp[N_];
    __shared__ float su[E_];
    int b = blockIdx.x, tid = threadIdx.x;
    for (int i = tid; i < N_ * E_; i += 128) sh[i] = g_h[b * N_ * E_ + i];
    if (tid < E_) sq[tid] = g_q[b * E_ + tid];
    __syncthreads();
    if (tid < N_) {
        float acc = 0.f;
        for (int e = 0; e < E_; e++) acc += sh[tid * E_ + e] * sq[e];
        sl[tid] = acc;
    }
    __syncthreads();
    if (tid == 0) {
        float m = sl[0];
        for (int n = 1; n < N_; n++) m = fmaxf(m, sl[n]);
        float s = 0.f;
        for (int n = 0; n < N_; n++) { float ev = expf(sl[n] - m); sp[n] = ev; s += ev; }
        float inv = 1.f / s;
        for (int n = 0; n < N_; n++) sp[n] *= inv;
    }
    __syncthreads();
    if (tid < E_) {
        float u = 0.f;
        for (int n = 0; n < N_; n++) u += sp[n] * sh[n * E_ + tid];
        su[tid] = u;
    }
    __syncthreads();
    if (tid < E_) {
        int f_ = tid;
        float acc = sq[f_] + H_b[f_];
        for (int e = 0; e < E_; e++) acc += su[e] * H_w[f_ * E_ + e];
        float ao = *a_out_p;
        g_ya[b * E_ + f_] = (acc >= 0.f) ? acc : ao * acc;
    }
}

// ============================================================
// K4: out[b][v] = ya[b] . R_w[v] + R_b[v]  (512 x 32000, K=100)
// ============================================================
#define NP 50
#define K4_SMEM_FLOATS (64*NP*2 * 2)
__global__ __launch_bounds__(256) void out_kernel(const float* __restrict__ R_w,
                                                  const float* __restrict__ R_b,
                                                  float* __restrict__ out) {
    extern __shared__ float osm[];
    float* sA2 = osm;
    float* sB2 = osm + 64 * NP * 2;
    int tid = threadIdx.x;
    int v0 = blockIdx.x * 64, b0 = blockIdx.y * 64;
    for (int i = tid; i < 64 * NP; i += 256) {
        int bi = i / NP, p = i % NP;
        const float* src = g_ya + (long)(b0 + bi) * E_ + 2 * p;
        sA2[(p * 64 + bi) * 2]     = src[0];
        sA2[(p * 64 + bi) * 2 + 1] = src[1];
    }
    for (int i = tid; i < 64 * NP; i += 256) {
        int vi = i / NP, p = i % NP;
        const float* src = R_w + (long)(v0 + vi) * E_ + 2 * p;
        sB2[(p * 64 + vi) * 2]     = src[0];
        sB2[(p * 64 + vi) * 2 + 1] = src[1];
    }
    __syncthreads();
    int bi4 = (tid >> 4) << 2;
    int vj  = tid & 15;
    unsigned long long acc2[4][4];
#pragma unroll
    for (int k = 0; k < 4; k++)
#pragma unroll
        for (int j = 0; j < 4; j++) acc2[k][j] = 0ull;
#pragma unroll 2
    for (int p = 0; p < NP; p++) {
        unsigned long long a2[4], b2[4];
#pragma unroll
        for (int k = 0; k < 4; k++) a2[k] = lds2(sA2 + (p * 64 + bi4 + k) * 2);
#pragma unroll
        for (int j = 0; j < 4; j++) b2[j] = lds2(sB2 + (p * 64 + vj + 16 * j) * 2);
#pragma unroll
        for (int k = 0; k < 4; k++)
#pragma unroll
            for (int j = 0; j < 4; j++) ffma2(acc2[k][j], a2[k], b2[j]);
    }
    float rb[4];
#pragma unroll
    for (int j = 0; j < 4; j++) rb[j] = R_b[v0 + vj + 16 * j];
#pragma unroll
    for (int k = 0; k < 4; k++) {
#pragma unroll
        for (int j = 0; j < 4; j++) {
            out[(long)(b0 + bi4 + k) * V_ + v0 + vj + 16 * j] = hadd2(acc2[k][j]) + rb[j];
        }
    }
}

// ============================================================
extern "C" void kernel_launch(void* const* d_in, const int* in_sizes, int n_in,
                              void* d_out, int out_size) {
    const float* in_data = (const float*)d_in[0];
    const float* f       = (const float*)d_in[1];
    const float* h0      = (const float*)d_in[2];
    const float* w_mem   = (const float*)d_in[3];
    const float* U_w     = (const float*)d_in[4];
    const float* V_w     = (const float*)d_in[5];
    const float* W_w     = (const float*)d_in[6];
    const float* a_dm    = (const float*)d_in[7];
    const float* H_w     = (const float*)d_in[8];
    const float* H_b     = (const float*)d_in[9];
    const float* R_w     = (const float*)d_in[10];
    const float* R_b     = (const float*)d_in[11];
    const float* a_out   = (const float*)d_in[12];
    float* out = (float*)d_out;

    cudaFuncSetAttribute(scan_mma_kernel, cudaFuncAttributeMaxDynamicSharedMemorySize,
                         SCAN_SMEM);
    const int k4_smem = K4_SMEM_FLOATS * (int)sizeof(float);
    cudaFuncSetAttribute(out_kernel, cudaFuncAttributeMaxDynamicSharedMemorySize,
                         k4_smem);

    infos_kernel<<<(B_ * NCH * E_ + 255) / 256, 256>>>(in_data, f);
    q_kernel<<<B_, 128>>>(in_data, f);
    scan_mma_kernel<<<B_ / NB, NTH, SCAN_SMEM>>>(U_w, V_w, W_w, w_mem, h0, a_dm);
    attn_kernel<<<B_, 128>>>(H_w, H_b, a_out);
    dim3 g4(V_ / 64, B_ / 64);
    out_kernel<<<g4, 256, k4_smem>>>(R_w, R_b, out);
}

// round 5
// speedup vs baseline: 2.2006x; 1.2157x over previous
#include <cuda_runtime.h>
#include <cuda_bf16.h>
#include <math.h>
#include <stdint.h>

#define B_   512
#define T_   1005
#define E_   100
#define L_   10
#define N_   20
#define V_   32000
#define NCH  100      // n_full = T/L
#define REST 5        // T % L

// ---- scratch (no allocations allowed) ----
__device__ float g_infos[NCH * B_ * E_];  // [t][b][e]
__device__ float g_h[B_ * N_ * E_];       // final h
__device__ float g_q[B_ * E_];
__device__ float g_ya[B_ * E_];           // prelu(y)

// ---- packed fp32x2 helpers (out_kernel) ----
__device__ __forceinline__ unsigned long long lds2(const float* p) {
    return *reinterpret_cast<const unsigned long long*>(p);
}
__device__ __forceinline__ void ffma2(unsigned long long& d,
                                      unsigned long long a,
                                      unsigned long long b) {
    asm("fma.rn.f32x2 %0, %1, %2, %0;" : "+l"(d) : "l"(a), "l"(b));
}
__device__ __forceinline__ float hadd2(unsigned long long v) {
    float lo, hi;
    asm("mov.b64 {%0, %1}, %2;" : "=f"(lo), "=f"(hi) : "l"(v));
    return lo + hi;
}

// ---- warp MMA helpers (portable PTX, sm_80+) ----
__device__ __forceinline__ uint32_t smem_u32(const void* p) {
    uint32_t a;
    asm("{ .reg .u64 t; cvta.to.shared.u64 t, %1; cvt.u32.u64 %0, t; }"
        : "=r"(a) : "l"(p));
    return a;
}
__device__ __forceinline__ void ldsm4(uint32_t* r, uint32_t a) {
    asm volatile("ldmatrix.sync.aligned.m8n8.x4.shared.b16 {%0,%1,%2,%3}, [%4];"
        : "=r"(r[0]), "=r"(r[1]), "=r"(r[2]), "=r"(r[3]) : "r"(a));
}
__device__ __forceinline__ void ldsm2(uint32_t* r, uint32_t a) {
    asm volatile("ldmatrix.sync.aligned.m8n8.x2.shared.b16 {%0,%1}, [%2];"
        : "=r"(r[0]), "=r"(r[1]) : "r"(a));
}
__device__ __forceinline__ void mma16816(float* c, const uint32_t* a, const uint32_t* b) {
    asm volatile(
        "mma.sync.aligned.m16n8k16.row.col.f32.bf16.bf16.f32 "
        "{%0,%1,%2,%3}, {%4,%5,%6,%7}, {%8,%9}, {%0,%1,%2,%3};"
        : "+f"(c[0]), "+f"(c[1]), "+f"(c[2]), "+f"(c[3])
        : "r"(a[0]), "r"(a[1]), "r"(a[2]), "r"(a[3]), "r"(b[0]), "r"(b[1]));
}
__device__ __forceinline__ uint32_t pack_bf2(float f0, float f1) {
    __nv_bfloat16 b0 = __float2bfloat16(f0);
    __nv_bfloat16 b1 = __float2bfloat16(f1);
    return (uint32_t)__bfloat16_as_ushort(b0) | ((uint32_t)__bfloat16_as_ushort(b1) << 16);
}
// split two fp32 into packed bf16 hi + residual lo
__device__ __forceinline__ void split2(float x0, float x1, uint32_t& hi, uint32_t& lo) {
    __nv_bfloat162 bh = __floats2bfloat162_rn(x0, x1);
    uint32_t h = *reinterpret_cast<uint32_t*>(&bh);
    float hf0 = __uint_as_float(h << 16);
    float hf1 = __uint_as_float(h & 0xffff0000u);
    __nv_bfloat162 bl = __floats2bfloat162_rn(x0 - hf0, x1 - hf1);
    hi = h;
    lo = *reinterpret_cast<uint32_t*>(&bl);
}

// ============================================================
// K1: infos[t][b][e] = sum_l f[l][e] * in[b][t*10+l][e]
// ============================================================
__global__ void infos_kernel(const float* __restrict__ in_data,
                             const float* __restrict__ f) {
    int idx = blockIdx.x * 256 + threadIdx.x;
    if (idx >= B_ * NCH * E_) return;
    int e = idx % E_;
    int bn = idx / E_;
    int n = bn % NCH;
    int b = bn / NCH;
    const float* ip = in_data + ((long)b * T_ + n * L_) * E_ + e;
    float acc = 0.f;
#pragma unroll
    for (int l = 0; l < L_; l++) acc += f[l * E_ + e] * ip[(long)l * E_];
    g_infos[(n * B_ + b) * E_ + e] = acc;
}

__global__ void q_kernel(const float* __restrict__ in_data,
                         const float* __restrict__ f) {
    int b = blockIdx.x;
    int e = threadIdx.x;
    if (e >= E_) return;
    const float* ip = in_data + ((long)b * T_ + NCH * L_) * E_ + e;
    float acc = 0.f;
#pragma unroll
    for (int l = 0; l < REST; l++) acc += f[l * E_ + e] * ip[(long)l * E_];
    g_q[b * E_ + e] = acc;
}

// ============================================================
// K2: persistent scan on warp MMA (bf16x3). 128 CTAs x 4 batches.
//     A fragments built in-register from fp32 sH (no A tile).
// ============================================================
#define NB   4
#define NTH  512
#define BST  240      // byte stride of U bf16 tile rows (15*16B, LDSM conflict-free)
#define HST  108      // float stride of sH rows
#define SST  104      // float stride of small arrays

#define OFF_BHI 0                          // 112*240 = 26880
#define OFF_BLO 26880                      // 26880
#define OFF_H   53760                      // 80*108*4 = 34560
#define OFF_W   88320                      // 100*100*4 = 40000
#define OFF_WM  128320                     // 20*104*4 = 8320
#define OFF_VW  136640                     // 8320
#define OFF_S   144960                     // 2*4*104*4 = 3328
#define OFF_SSW 148288                     // 4*104*4 = 1664
#define OFF_G   149952                     // 320
#define OFF_GP  150272                     // 640
#define SCAN_SMEM 150912

__global__ __launch_bounds__(NTH, 1) void scan_mma_kernel(
    const float* __restrict__ U_w, const float* __restrict__ V_w,
    const float* __restrict__ W_w, const float* __restrict__ w_mem,
    const float* __restrict__ h0,  const float* __restrict__ a_dm_p)
{
    extern __shared__ char smc[];
    float* sH  = (float*)(smc + OFF_H);
    float* sW  = (float*)(smc + OFF_W);
    float* sWm = (float*)(smc + OFF_WM);
    float* sVw = (float*)(smc + OFF_VW);
    float* sS  = (float*)(smc + OFF_S);
    float* sSW = (float*)(smc + OFF_SSW);
    float* sG  = (float*)(smc + OFF_G);
    float* sGp = (float*)(smc + OFF_GP);

    const int tid = threadIdx.x;
    const int w = tid >> 5;
    const int lane = tid & 31;
    const int b0g = blockIdx.x * NB;
    const float adm = *a_dm_p;
    const uint32_t smb = smem_u32(smc);

    // ---- zero B tiles + sH (pad cols must be zero) ----
    for (int i = tid; i < OFF_W / 4; i += NTH) ((uint32_t*)smc)[i] = 0;
    __syncthreads();

    // ---- stage U (bf16 hi/lo), W, w_mem, h init ----
    for (int i = tid; i < E_ * 50; i += NTH) {
        int f_ = i / 50, p = i % 50;
        float2 uv = *(const float2*)(U_w + f_ * E_ + 2 * p);
        uint32_t hi, lo;
        split2(uv.x, uv.y, hi, lo);
        *(uint32_t*)(smc + OFF_BHI + f_ * BST + p * 4) = hi;
        *(uint32_t*)(smc + OFF_BLO + f_ * BST + p * 4) = lo;
    }
    for (int i = tid; i < E_ * E_; i += NTH) sW[i] = W_w[i];
    for (int i = tid; i < N_ * E_; i += NTH) {
        int n_ = i / E_, e_ = i % E_;
        sWm[n_ * SST + e_] = w_mem[i];
    }
    for (int i = tid; i < 80 * E_; i += NTH) {
        int row = i / E_, e_ = i % E_;
        sH[row * HST + e_] = h0[(row % N_) * E_ + e_];
    }
    if (tid < 80) { sGp[2 * tid] = 1.f; sGp[2 * tid + 1] = 0.f; }
    if (tid < NB * E_) {
        int bi = tid / E_, e_ = tid % E_;
        sS[bi * SST + e_] = g_infos[((long)0 * B_ + b0g + bi) * E_ + e_];
    }
    __syncthreads();
    // Vw[n][f] = w_mem[n] . V_w[f] (one-time)
    for (int i = tid; i < N_ * E_; i += NTH) {
        int n_ = i / E_, f_ = i % E_;
        float acc = 0.f;
        for (int e_ = 0; e_ < E_; e_++) acc += sWm[n_ * SST + e_] * V_w[f_ * E_ + e_];
        sVw[n_ * SST + f_] = acc;
    }
    __syncthreads();

    const int stripe = w >> 1, nh = w & 1;
    const int m0 = stripe * 16;
    const int qr = lane >> 2, qc = lane & 3;
    const int r0 = m0 + qr, r1 = r0 + 8;

    for (int t = 0; t < NCH; t++) {
        const float* sScur = sS + (t & 1) * NB * SST;

        // ================= phase A =================
        float acc[7][4];
        float inv0 = 0.f, inv1 = 0.f;
        if (w < 10) {
            inv0 = rsqrtf(sGp[2 * r0] + sGp[2 * r0 + 1]);
            inv1 = rsqrtf(sGp[2 * r1] + sGp[2 * r1 + 1]);
#pragma unroll
            for (int j = 0; j < 7; j++)
#pragma unroll
                for (int q = 0; q < 4; q++) acc[j][q] = 0.f;
            const uint32_t bhBase = smb + OFF_BHI;
            const int grp = lane >> 3, lr = lane & 7;
#pragma unroll
            for (int k = 0; k < 7; k++) {
                // A fragments directly from fp32 sH
                int kc = k * 16 + 2 * qc;
                float2 v00 = *(const float2*)(sH + r0 * HST + kc);
                float2 v10 = *(const float2*)(sH + r1 * HST + kc);
                float2 v01 = *(const float2*)(sH + r0 * HST + kc + 8);
                float2 v11 = *(const float2*)(sH + r1 * HST + kc + 8);
                uint32_t ah[4], al[4];
                split2(v00.x * inv0, v00.y * inv0, ah[0], al[0]);
                split2(v10.x * inv1, v10.y * inv1, ah[1], al[1]);
                split2(v01.x * inv0, v01.y * inv0, ah[2], al[2]);
                split2(v11.x * inv1, v11.y * inv1, ah[3], al[3]);
                // B fragments: 3x ldsm4 (tile pairs) + 1x ldsm2
                uint32_t bh[14], bl[14];
#pragma unroll
                for (int pq = 0; pq < 3; pq++) {
                    int t0 = nh * 7 + pq * 2;
                    uint32_t addr = bhBase + (uint32_t)((t0 * 8 + lr + (grp >> 1) * 8) * BST
                                  + k * 32 + (grp & 1) * 16);
                    ldsm4(&bh[pq * 4], addr);
                    ldsm4(&bl[pq * 4], addr + 26880u);
                }
                {
                    int t6 = nh * 7 + 6;
                    uint32_t addr = bhBase + (uint32_t)((t6 * 8 + lr) * BST
                                  + k * 32 + ((lane >> 3) & 1) * 16);
                    ldsm2(&bh[12], addr);
                    ldsm2(&bl[12], addr + 26880u);
                }
#pragma unroll
                for (int j = 0; j < 7; j++) {
                    mma16816(acc[j], ah, &bh[2 * j]);
                    mma16816(acc[j], al, &bh[2 * j]);
                    mma16816(acc[j], ah, &bl[2 * j]);
                }
            }
        } else {
            int i = tid - 320;
            if (i < 100) {
                // sSW[bi][f=i] = s[bi] . W[f]
                int f_ = i;
                float a0 = 0.f, a1 = 0.f, a2 = 0.f, a3 = 0.f;
                const float* wp = sW + f_ * E_;
                for (int e4 = 0; e4 < 25; e4++) {
                    float4 wv = *(const float4*)(wp + e4 * 4);
                    float4 s0 = *(const float4*)(sScur + 0 * SST + e4 * 4);
                    float4 s1 = *(const float4*)(sScur + 1 * SST + e4 * 4);
                    float4 s2 = *(const float4*)(sScur + 2 * SST + e4 * 4);
                    float4 s3 = *(const float4*)(sScur + 3 * SST + e4 * 4);
                    a0 += wv.x * s0.x + wv.y * s0.y + wv.z * s0.z + wv.w * s0.w;
                    a1 += wv.x * s1.x + wv.y * s1.y + wv.z * s1.z + wv.w * s1.w;
                    a2 += wv.x * s2.x + wv.y * s2.y + wv.z * s2.z + wv.w * s2.w;
                    a3 += wv.x * s3.x + wv.y * s3.y + wv.z * s3.z + wv.w * s3.w;
                }
                sSW[0 * SST + f_] = a0;
                sSW[1 * SST + f_] = a1;
                sSW[2 * SST + f_] = a2;
                sSW[3 * SST + f_] = a3;
            } else if (i < 180) {
                // gate
                int row = i - 100;
                int bi = row / N_, ne = row % N_;
                const float* hp = sH + row * HST;
                const float* wp = sWm + ne * SST;
                const float* sp = sScur + bi * SST;
                float hs = 0.f, ws = 0.f;
                for (int e4 = 0; e4 < 25; e4++) {
                    float4 hv = *(const float4*)(hp + e4 * 4);
                    float4 wv = *(const float4*)(wp + e4 * 4);
                    float4 sv = *(const float4*)(sp + e4 * 4);
                    hs += hv.x * sv.x + hv.y * sv.y + hv.z * sv.z + hv.w * sv.w;
                    ws += wv.x * sv.x + wv.y * sv.y + wv.z * sv.z + wv.w * sv.w;
                }
                float inv = rsqrtf(sGp[2 * row] + sGp[2 * row + 1]);
                sG[row] = 1.f / (1.f + expf(-(inv * hs + ws)));
            }
        }
        __syncthreads();

        // ================= phase B =================
        if (w < 10) {
            float g0 = sG[r0], g1 = sG[r1];
            int bi0 = r0 / N_, ne0 = r0 % N_;
            int bi1 = r1 / N_, ne1 = r1 % N_;
            float ssq0 = 0.f, ssq1 = 0.f;
#pragma unroll
            for (int j = 0; j < 7; j++) {
                int f0 = (nh * 7 + j) * 8 + 2 * qc;
                if (f0 < 100) {
                    float2 vw0 = *(const float2*)(sVw + ne0 * SST + f0);
                    float2 sw0 = *(const float2*)(sSW + bi0 * SST + f0);
                    float2 hv0 = *(const float2*)(sH + r0 * HST + f0);
                    float c0 = acc[j][0] + vw0.x + sw0.x;
                    float c1 = acc[j][1] + vw0.y + sw0.y;
                    c0 = (c0 >= 0.f) ? c0 : adm * c0;
                    c1 = (c1 >= 0.f) ? c1 : adm * c1;
                    float n0v = hv0.x * inv0 + g0 * c0;
                    float n1v = hv0.y * inv0 + g0 * c1;
                    *(float2*)(sH + r0 * HST + f0) = make_float2(n0v, n1v);
                    ssq0 += n0v * n0v + n1v * n1v;

                    float2 vw1 = *(const float2*)(sVw + ne1 * SST + f0);
                    float2 sw1 = *(const float2*)(sSW + bi1 * SST + f0);
                    float2 hv1 = *(const float2*)(sH + r1 * HST + f0);
                    float d0 = acc[j][2] + vw1.x + sw1.x;
                    float d1 = acc[j][3] + vw1.y + sw1.y;
                    d0 = (d0 >= 0.f) ? d0 : adm * d0;
                    d1 = (d1 >= 0.f) ? d1 : adm * d1;
                    float m0v = hv1.x * inv1 + g1 * d0;
                    float m1v = hv1.y * inv1 + g1 * d1;
                    *(float2*)(sH + r1 * HST + f0) = make_float2(m0v, m1v);
                    ssq1 += m0v * m0v + m1v * m1v;
                }
            }
            ssq0 += __shfl_xor_sync(0xffffffffu, ssq0, 1);
            ssq0 += __shfl_xor_sync(0xffffffffu, ssq0, 2);
            ssq1 += __shfl_xor_sync(0xffffffffu, ssq1, 1);
            ssq1 += __shfl_xor_sync(0xffffffffu, ssq1, 2);
            if (qc == 0) {
                sGp[2 * r0 + nh] = ssq0;
                sGp[2 * r1 + nh] = ssq1;
            }
        } else if (t + 1 < NCH) {
            // prefetch s_{t+1}
            for (int i = tid - 320; i < NB * E_; i += 192) {
                int bi = i / E_, e_ = i % E_;
                sS[((t + 1) & 1) * NB * SST + bi * SST + e_] =
                    g_infos[((long)(t + 1) * B_ + b0g + bi) * E_ + e_];
            }
        }
        __syncthreads();
    }

    // ---- final normalize + write h ----
    for (int i = tid; i < 80 * E_; i += NTH) {
        int row = i / E_, e_ = i % E_;
        float inv = rsqrtf(sGp[2 * row] + sGp[2 * row + 1]);
        g_h[(long)(b0g + row / N_) * N_ * E_ + (row % N_) * E_ + e_] =
            sH[row * HST + e_] * inv;
    }
}

// ============================================================
// K3: attention over entities + hidden head, per batch
// ============================================================
__global__ void attn_kernel(const float* __restrict__ H_w,
                            const float* __restrict__ H_b,
                            const float* __restrict__ a_out_p) {
    __shared__ float sh[N_ * E_];
    __shared__ float sq[E_];
    __shared__ float sl[N_];
    __shared__ float sp[N_];
    __shared__ float su[E_];
    int b = blockIdx.x, tid = threadIdx.x;
    for (int i = tid; i < N_ * E_; i += 128) sh[i] = g_h[b * N_ * E_ + i];
    if (tid < E_) sq[tid] = g_q[b * E_ + tid];
    __syncthreads();
    if (tid < N_) {
        float acc = 0.f;
        for (int e = 0; e < E_; e++) acc += sh[tid * E_ + e] * sq[e];
        sl[tid] = acc;
    }
    __syncthreads();
    if (tid == 0) {
        float m = sl[0];
        for (int n = 1; n < N_; n++) m = fmaxf(m, sl[n]);
        float s = 0.f;
        for (int n = 0; n < N_; n++) { float ev = expf(sl[n] - m); sp[n] = ev; s += ev; }
        float inv = 1.f / s;
        for (int n = 0; n < N_; n++) sp[n] *= inv;
    }
    __syncthreads();
    if (tid < E_) {
        float u = 0.f;
        for (int n = 0; n < N_; n++) u += sp[n] * sh[n * E_ + tid];
        su[tid] = u;
    }
    __syncthreads();
    if (tid < E_) {
        int f_ = tid;
        float acc = sq[f_] + H_b[f_];
        for (int e = 0; e < E_; e++) acc += su[e] * H_w[f_ * E_ + e];
        float ao = *a_out_p;
        g_ya[b * E_ + f_] = (acc >= 0.f) ? acc : ao * acc;
    }
}

// ============================================================
// K4: out[b][v] = ya[b] . R_w[v] + R_b[v]  (512 x 32000, K=100)
//     128x64 tiles, FFMA2.
// ============================================================
#define NP 50
#define K4_SMEM_FLOATS (128*NP*2 + 64*NP*2)
__global__ __launch_bounds__(256) void out_kernel(const float* __restrict__ R_w,
                                                  const float* __restrict__ R_b,
                                                  float* __restrict__ out) {
    extern __shared__ float osm[];
    float* sA2 = osm;                 // [p][bi] pairs, 128 rows
    float* sB2 = osm + 128 * NP * 2;  // [p][vi] pairs, 64 cols
    int tid = threadIdx.x;
    int v0 = blockIdx.x * 64, b0 = blockIdx.y * 128;
    for (int i = tid; i < 128 * NP; i += 256) {
        int bi = i / NP, p = i % NP;
        float2 v = *(const float2*)(g_ya + (long)(b0 + bi) * E_ + 2 * p);
        sA2[(p * 128 + bi) * 2]     = v.x;
        sA2[(p * 128 + bi) * 2 + 1] = v.y;
    }
    for (int i = tid; i < 64 * NP; i += 256) {
        int vi = i / NP, p = i % NP;
        float2 v = *(const float2*)(R_w + (long)(v0 + vi) * E_ + 2 * p);
        sB2[(p * 64 + vi) * 2]     = v.x;
        sB2[(p * 64 + vi) * 2 + 1] = v.y;
    }
    __syncthreads();
    int bi8 = (tid >> 4) << 3;    // rows bi8..bi8+7
    int vj  = tid & 15;           // cols {vj, vj+16, vj+32, vj+48}
    unsigned long long acc2[8][4];
#pragma unroll
    for (int k = 0; k < 8; k++)
#pragma unroll
        for (int j = 0; j < 4; j++) acc2[k][j] = 0ull;
#pragma unroll 2
    for (int p = 0; p < NP; p++) {
        unsigned long long a2[8], b2[4];
#pragma unroll
        for (int j = 0; j < 4; j++) b2[j] = lds2(sB2 + (p * 64 + vj + 16 * j) * 2);
#pragma unroll
        for (int k = 0; k < 8; k++) a2[k] = lds2(sA2 + (p * 128 + bi8 + k) * 2);
#pragma unroll
        for (int k = 0; k < 8; k++)
#pragma unroll
            for (int j = 0; j < 4; j++) ffma2(acc2[k][j], a2[k], b2[j]);
    }
    float rb[4];
#pragma unroll
    for (int j = 0; j < 4; j++) rb[j] = R_b[v0 + vj + 16 * j];
#pragma unroll
    for (int k = 0; k < 8; k++) {
#pragma unroll
        for (int j = 0; j < 4; j++) {
            out[(long)(b0 + bi8 + k) * V_ + v0 + vj + 16 * j] = hadd2(acc2[k][j]) + rb[j];
        }
    }
}

// ============================================================
extern "C" void kernel_launch(void* const* d_in, const int* in_sizes, int n_in,
                              void* d_out, int out_size) {
    const float* in_data = (const float*)d_in[0];
    const float* f       = (const float*)d_in[1];
    const float* h0      = (const float*)d_in[2];
    const float* w_mem   = (const float*)d_in[3];
    const float* U_w     = (const float*)d_in[4];
    const float* V_w     = (const float*)d_in[5];
    const float* W_w     = (const float*)d_in[6];
    const float* a_dm    = (const float*)d_in[7];
    const float* H_w     = (const float*)d_in[8];
    const float* H_b     = (const float*)d_in[9];
    const float* R_w     = (const float*)d_in[10];
    const float* R_b     = (const float*)d_in[11];
    const float* a_out   = (const float*)d_in[12];
    float* out = (float*)d_out;

    cudaFuncSetAttribute(scan_mma_kernel, cudaFuncAttributeMaxDynamicSharedMemorySize,
                         SCAN_SMEM);
    const int k4_smem = K4_SMEM_FLOATS * (int)sizeof(float);
    cudaFuncSetAttribute(out_kernel, cudaFuncAttributeMaxDynamicSharedMemorySize,
                         k4_smem);

    infos_kernel<<<(B_ * NCH * E_ + 255) / 256, 256>>>(in_data, f);
    q_kernel<<<B_, 128>>>(in_data, f);
    scan_mma_kernel<<<B_ / NB, NTH, SCAN_SMEM>>>(U_w, V_w, W_w, w_mem, h0, a_dm);
    attn_kernel<<<B_, 128>>>(H_w, H_b, a_out);
    dim3 g4(V_ / 64, B_ / 128);
    out_kernel<<<g4, 256, k4_smem>>>(R_w, R_b, out);
}

// round 6
// speedup vs baseline: 2.2959x; 1.0433x over previous
#include <cuda_runtime.h>
#include <cuda_bf16.h>
#include <math.h>
#include <stdint.h>

#define B_   512
#define T_   1005
#define E_   100
#define L_   10
#define N_   20
#define V_   32000
#define NCH  100      // n_full = T/L
#define REST 5        // T % L

// ---- scratch (no allocations allowed) ----
__device__ float g_infos[NCH * B_ * E_];  // [t][b][e]
__device__ float g_h[B_ * N_ * E_];       // final h
__device__ float g_q[B_ * E_];
__device__ float g_ya[B_ * E_];           // prelu(y)

// ---- packed fp32x2 helpers (out_kernel) ----
__device__ __forceinline__ unsigned long long lds2(const float* p) {
    return *reinterpret_cast<const unsigned long long*>(p);
}
__device__ __forceinline__ void ffma2(unsigned long long& d,
                                      unsigned long long a,
                                      unsigned long long b) {
    asm("fma.rn.f32x2 %0, %1, %2, %0;" : "+l"(d) : "l"(a), "l"(b));
}
__device__ __forceinline__ float hadd2(unsigned long long v) {
    float lo, hi;
    asm("mov.b64 {%0, %1}, %2;" : "=f"(lo), "=f"(hi) : "l"(v));
    return lo + hi;
}

// ---- warp MMA helpers (portable PTX, sm_80+) ----
__device__ __forceinline__ uint32_t smem_u32(const void* p) {
    uint32_t a;
    asm("{ .reg .u64 t; cvta.to.shared.u64 t, %1; cvt.u32.u64 %0, t; }"
        : "=r"(a) : "l"(p));
    return a;
}
__device__ __forceinline__ void ldsm4(uint32_t* r, uint32_t a) {
    asm volatile("ldmatrix.sync.aligned.m8n8.x4.shared.b16 {%0,%1,%2,%3}, [%4];"
        : "=r"(r[0]), "=r"(r[1]), "=r"(r[2]), "=r"(r[3]) : "r"(a));
}
__device__ __forceinline__ void ldsm2(uint32_t* r, uint32_t a) {
    asm volatile("ldmatrix.sync.aligned.m8n8.x2.shared.b16 {%0,%1}, [%2];"
        : "=r"(r[0]), "=r"(r[1]) : "r"(a));
}
__device__ __forceinline__ void mma16816(float* c, const uint32_t* a, const uint32_t* b) {
    asm volatile(
        "mma.sync.aligned.m16n8k16.row.col.f32.bf16.bf16.f32 "
        "{%0,%1,%2,%3}, {%4,%5,%6,%7}, {%8,%9}, {%0,%1,%2,%3};"
        : "+f"(c[0]), "+f"(c[1]), "+f"(c[2]), "+f"(c[3])
        : "r"(a[0]), "r"(a[1]), "r"(a[2]), "r"(a[3]), "r"(b[0]), "r"(b[1]));
}
// split two fp32 into packed bf16 hi + residual lo
__device__ __forceinline__ void split2(float x0, float x1, uint32_t& hi, uint32_t& lo) {
    __nv_bfloat162 bh = __floats2bfloat162_rn(x0, x1);
    uint32_t h = *reinterpret_cast<uint32_t*>(&bh);
    float hf0 = __uint_as_float(h << 16);
    float hf1 = __uint_as_float(h & 0xffff0000u);
    __nv_bfloat162 bl = __floats2bfloat162_rn(x0 - hf0, x1 - hf1);
    hi = h;
    lo = *reinterpret_cast<uint32_t*>(&bl);
}

// ============================================================
// K1: infos[t][b][e] = sum_l f[l][e] * in[b][t*10+l][e]
// ============================================================
__global__ void infos_kernel(const float* __restrict__ in_data,
                             const float* __restrict__ f) {
    int idx = blockIdx.x * 256 + threadIdx.x;
    if (idx >= B_ * NCH * E_) return;
    int e = idx % E_;
    int bn = idx / E_;
    int n = bn % NCH;
    int b = bn / NCH;
    const float* ip = in_data + ((long)b * T_ + n * L_) * E_ + e;
    float acc = 0.f;
#pragma unroll
    for (int l = 0; l < L_; l++) acc += f[l * E_ + e] * ip[(long)l * E_];
    g_infos[(n * B_ + b) * E_ + e] = acc;
}

__global__ void q_kernel(const float* __restrict__ in_data,
                         const float* __restrict__ f) {
    int b = blockIdx.x;
    int e = threadIdx.x;
    if (e >= E_) return;
    const float* ip = in_data + ((long)b * T_ + NCH * L_) * E_ + e;
    float acc = 0.f;
#pragma unroll
    for (int l = 0; l < REST; l++) acc += f[l * E_ + e] * ip[(long)l * E_];
    g_q[b * E_ + e] = acc;
}

// ============================================================
// K2: persistent scan on warp MMA (bf16x3). 128 CTAs x 4 batches.
//     MMA runs on UNNORMALIZED h (norm folded into epilogue scalar);
//     A tiles written once per step by the epilogue.
// ============================================================
#define NB   4
#define NTH  512
#define BST  240      // byte stride of bf16 tile rows (15*16B, LDSM conflict-free)
#define HST  108      // float stride of sH rows
#define SST  104      // float stride of small arrays

#define OFF_AHI 0                          // 80*240  = 19200
#define OFF_ALO 19200                      // 19200
#define OFF_BHI 38400                      // 112*240 = 26880
#define OFF_BLO 65280                      // 26880
#define OFF_H   92160                      // 80*108*4 = 34560
#define OFF_W   126720                     // 100*100*4 = 40000
#define OFF_WM  166720                     // 20*104*4 = 8320
#define OFF_VW  175040                     // 8320
#define OFF_S   183360                     // 2*4*104*4 = 3328
#define OFF_SSW 186688                     // 4*104*4 = 1664
#define OFF_G   188352                     // 320
#define OFF_GP  188672                     // 640
#define SCAN_SMEM 189312

__global__ __launch_bounds__(NTH, 1) void scan_mma_kernel(
    const float* __restrict__ U_w, const float* __restrict__ V_w,
    const float* __restrict__ W_w, const float* __restrict__ w_mem,
    const float* __restrict__ h0,  const float* __restrict__ a_dm_p)
{
    extern __shared__ char smc[];
    float* sH  = (float*)(smc + OFF_H);
    float* sW  = (float*)(smc + OFF_W);
    float* sWm = (float*)(smc + OFF_WM);
    float* sVw = (float*)(smc + OFF_VW);
    float* sS  = (float*)(smc + OFF_S);
    float* sSW = (float*)(smc + OFF_SSW);
    float* sG  = (float*)(smc + OFF_G);
    float* sGp = (float*)(smc + OFF_GP);

    const int tid = threadIdx.x;
    const int w = tid >> 5;
    const int lane = tid & 31;
    const int b0g = blockIdx.x * NB;
    const float adm = *a_dm_p;
    const uint32_t smb = smem_u32(smc);

    // ---- zero A+B tiles (pad rows/cols must stay zero) ----
    for (int i = tid; i < OFF_H / 4; i += NTH) ((uint32_t*)smc)[i] = 0;
    __syncthreads();

    // ---- stage U (bf16 hi/lo), W, w_mem, h init + A tiles from h0 ----
    for (int i = tid; i < E_ * 50; i += NTH) {
        int f_ = i / 50, p = i % 50;
        float2 uv = *(const float2*)(U_w + f_ * E_ + 2 * p);
        uint32_t hi, lo;
        split2(uv.x, uv.y, hi, lo);
        *(uint32_t*)(smc + OFF_BHI + f_ * BST + p * 4) = hi;
        *(uint32_t*)(smc + OFF_BLO + f_ * BST + p * 4) = lo;
    }
    for (int i = tid; i < E_ * E_; i += NTH) sW[i] = W_w[i];
    for (int i = tid; i < N_ * E_; i += NTH) {
        int n_ = i / E_, e_ = i % E_;
        sWm[n_ * SST + e_] = w_mem[i];
    }
    for (int i = tid; i < 80 * 50; i += NTH) {
        int row = i / 50, p = i % 50;
        float2 hv = *(const float2*)(h0 + (row % N_) * E_ + 2 * p);
        *(float2*)(sH + row * HST + 2 * p) = hv;
        uint32_t hi, lo;
        split2(hv.x, hv.y, hi, lo);
        *(uint32_t*)(smc + OFF_AHI + row * BST + p * 4) = hi;
        *(uint32_t*)(smc + OFF_ALO + row * BST + p * 4) = lo;
    }
    if (tid < 80) { sGp[2 * tid] = 1.f; sGp[2 * tid + 1] = 0.f; }
    if (tid < NB * E_) {
        int bi = tid / E_, e_ = tid % E_;
        sS[bi * SST + e_] = g_infos[((long)0 * B_ + b0g + bi) * E_ + e_];
    }
    __syncthreads();
    // Vw[n][f] = w_mem[n] . V_w[f] (one-time)
    for (int i = tid; i < N_ * E_; i += NTH) {
        int n_ = i / E_, f_ = i % E_;
        float acc = 0.f;
        for (int e_ = 0; e_ < E_; e_++) acc += sWm[n_ * SST + e_] * V_w[f_ * E_ + e_];
        sVw[n_ * SST + f_] = acc;
    }
    __syncthreads();

    const int stripe = w >> 1, nh = w & 1;
    const int m0 = stripe * 16;
    const int qr = lane >> 2, qc = lane & 3;
    const int r0 = m0 + qr, r1 = r0 + 8;

    for (int t = 0; t < NCH; t++) {
        const float* sScur = sS + (t & 1) * NB * SST;

        // ================= phase A: MMA on unnormalized h =================
        float acc[7][4];
        float inv0 = 0.f, inv1 = 0.f;
        if (w < 10) {
            inv0 = rsqrtf(sGp[2 * r0] + sGp[2 * r0 + 1]);
            inv1 = rsqrtf(sGp[2 * r1] + sGp[2 * r1 + 1]);
#pragma unroll
            for (int j = 0; j < 7; j++)
#pragma unroll
                for (int q = 0; q < 4; q++) acc[j][q] = 0.f;
            const uint32_t aBase = smb + OFF_AHI;
            const uint32_t bhBase = smb + OFF_BHI;
            const int grp = lane >> 3, lr = lane & 7;
#pragma unroll
            for (int k = 0; k < 7; k++) {
                // A fragments via ldmatrix (hi + lo)
                uint32_t ah[4], al[4];
                uint32_t aaddr = aBase + (uint32_t)((m0 + lr + ((grp & 1) << 3)) * BST
                               + k * 32 + ((grp >> 1) << 4));
                ldsm4(ah, aaddr);
                ldsm4(al, aaddr + 19200u);
                // B fragments: 3x ldsm4 (tile pairs) + 1x ldsm2
                uint32_t bh[14], bl[14];
#pragma unroll
                for (int pq = 0; pq < 3; pq++) {
                    int t0 = nh * 7 + pq * 2;
                    uint32_t addr = bhBase + (uint32_t)((t0 * 8 + lr + (grp >> 1) * 8) * BST
                                  + k * 32 + (grp & 1) * 16);
                    ldsm4(&bh[pq * 4], addr);
                    ldsm4(&bl[pq * 4], addr + 26880u);
                }
                {
                    int t6 = nh * 7 + 6;
                    uint32_t addr = bhBase + (uint32_t)((t6 * 8 + lr) * BST
                                  + k * 32 + ((lane >> 3) & 1) * 16);
                    ldsm2(&bh[12], addr);
                    ldsm2(&bl[12], addr + 26880u);
                }
#pragma unroll
                for (int j = 0; j < 7; j++) {
                    mma16816(acc[j], ah, &bh[2 * j]);
                    mma16816(acc[j], al, &bh[2 * j]);
                    mma16816(acc[j], ah, &bl[2 * j]);
                }
            }
        } else {
            int i = tid - 320;
            if (i < 100) {
                // sSW[bi][f=i] = s[bi] . W[f]
                int f_ = i;
                float a0 = 0.f, a1 = 0.f, a2 = 0.f, a3 = 0.f;
                const float* wp = sW + f_ * E_;
                for (int e4 = 0; e4 < 25; e4++) {
                    float4 wv = *(const float4*)(wp + e4 * 4);
                    float4 s0 = *(const float4*)(sScur + 0 * SST + e4 * 4);
                    float4 s1 = *(const float4*)(sScur + 1 * SST + e4 * 4);
                    float4 s2 = *(const float4*)(sScur + 2 * SST + e4 * 4);
                    float4 s3 = *(const float4*)(sScur + 3 * SST + e4 * 4);
                    a0 += wv.x * s0.x + wv.y * s0.y + wv.z * s0.z + wv.w * s0.w;
                    a1 += wv.x * s1.x + wv.y * s1.y + wv.z * s1.z + wv.w * s1.w;
                    a2 += wv.x * s2.x + wv.y * s2.y + wv.z * s2.z + wv.w * s2.w;
                    a3 += wv.x * s3.x + wv.y * s3.y + wv.z * s3.z + wv.w * s3.w;
                }
                sSW[0 * SST + f_] = a0;
                sSW[1 * SST + f_] = a1;
                sSW[2 * SST + f_] = a2;
                sSW[3 * SST + f_] = a3;
            } else if (i < 180) {
                // gate
                int row = i - 100;
                int bi = row / N_, ne = row % N_;
                const float* hp = sH + row * HST;
                const float* wp = sWm + ne * SST;
                const float* sp = sScur + bi * SST;
                float hs = 0.f, ws = 0.f;
                for (int e4 = 0; e4 < 25; e4++) {
                    float4 hv = *(const float4*)(hp + e4 * 4);
                    float4 wv = *(const float4*)(wp + e4 * 4);
                    float4 sv = *(const float4*)(sp + e4 * 4);
                    hs += hv.x * sv.x + hv.y * sv.y + hv.z * sv.z + hv.w * sv.w;
                    ws += wv.x * sv.x + wv.y * sv.y + wv.z * sv.z + wv.w * sv.w;
                }
                float inv = rsqrtf(sGp[2 * row] + sGp[2 * row + 1]);
                sG[row] = 1.f / (1.f + expf(-(inv * hs + ws)));
            }
        }
        __syncthreads();

        // ================= phase B: epilogue + A-tile store =================
        if (w < 10) {
            float g0 = sG[r0], g1 = sG[r1];
            int bi0 = r0 / N_, ne0 = r0 % N_;
            int bi1 = r1 / N_, ne1 = r1 % N_;
            float ssq0 = 0.f, ssq1 = 0.f;
#pragma unroll
            for (int j = 0; j < 7; j++) {
                int f0 = (nh * 7 + j) * 8 + 2 * qc;
                if (f0 < 100) {
                    float2 vw0 = *(const float2*)(sVw + ne0 * SST + f0);
                    float2 sw0 = *(const float2*)(sSW + bi0 * SST + f0);
                    float2 hv0 = *(const float2*)(sH + r0 * HST + f0);
                    float c0 = acc[j][0] * inv0 + vw0.x + sw0.x;
                    float c1 = acc[j][1] * inv0 + vw0.y + sw0.y;
                    c0 = (c0 >= 0.f) ? c0 : adm * c0;
                    c1 = (c1 >= 0.f) ? c1 : adm * c1;
                    float n0v = hv0.x * inv0 + g0 * c0;
                    float n1v = hv0.y * inv0 + g0 * c1;
                    *(float2*)(sH + r0 * HST + f0) = make_float2(n0v, n1v);
                    ssq0 += n0v * n0v + n1v * n1v;
                    uint32_t hi0, lo0;
                    split2(n0v, n1v, hi0, lo0);
                    *(uint32_t*)(smc + OFF_AHI + r0 * BST + f0 * 2) = hi0;
                    *(uint32_t*)(smc + OFF_ALO + r0 * BST + f0 * 2) = lo0;

                    float2 vw1 = *(const float2*)(sVw + ne1 * SST + f0);
                    float2 sw1 = *(const float2*)(sSW + bi1 * SST + f0);
                    float2 hv1 = *(const float2*)(sH + r1 * HST + f0);
                    float d0 = acc[j][2] * inv1 + vw1.x + sw1.x;
                    float d1 = acc[j][3] * inv1 + vw1.y + sw1.y;
                    d0 = (d0 >= 0.f) ? d0 : adm * d0;
                    d1 = (d1 >= 0.f) ? d1 : adm * d1;
                    float m0v = hv1.x * inv1 + g1 * d0;
                    float m1v = hv1.y * inv1 + g1 * d1;
                    *(float2*)(sH + r1 * HST + f0) = make_float2(m0v, m1v);
                    ssq1 += m0v * m0v + m1v * m1v;
                    uint32_t hi1, lo1;
                    split2(m0v, m1v, hi1, lo1);
                    *(uint32_t*)(smc + OFF_AHI + r1 * BST + f0 * 2) = hi1;
                    *(uint32_t*)(smc + OFF_ALO + r1 * BST + f0 * 2) = lo1;
                }
            }
            ssq0 += __shfl_xor_sync(0xffffffffu, ssq0, 1);
            ssq0 += __shfl_xor_sync(0xffffffffu, ssq0, 2);
            ssq1 += __shfl_xor_sync(0xffffffffu, ssq1, 1);
            ssq1 += __shfl_xor_sync(0xffffffffu, ssq1, 2);
            if (qc == 0) {
                sGp[2 * r0 + nh] = ssq0;
                sGp[2 * r1 + nh] = ssq1;
            }
        } else if (t + 1 < NCH) {
            // prefetch s_{t+1}
            for (int i = tid - 320; i < NB * E_; i += 192) {
                int bi = i / E_, e_ = i % E_;
                sS[((t + 1) & 1) * NB * SST + bi * SST + e_] =
                    g_infos[((long)(t + 1) * B_ + b0g + bi) * E_ + e_];
            }
        }
        __syncthreads();
    }

    // ---- final normalize + write h ----
    for (int i = tid; i < 80 * E_; i += NTH) {
        int row = i / E_, e_ = i % E_;
        float inv = rsqrtf(sGp[2 * row] + sGp[2 * row + 1]);
        g_h[(long)(b0g + row / N_) * N_ * E_ + (row % N_) * E_ + e_] =
            sH[row * HST + e_] * inv;
    }
}

// ============================================================
// K3: attention over entities + hidden head, per batch
// ============================================================
__global__ void attn_kernel(const float* __restrict__ H_w,
                            const float* __restrict__ H_b,
                            const float* __restrict__ a_out_p) {
    __shared__ float sh[N_ * E_];
    __shared__ float sq[E_];
    __shared__ float sl[N_];
    __shared__ float sp[N_];
    __shared__ float su[E_];
    int b = blockIdx.x, tid = threadIdx.x;
    for (int i = tid; i < N_ * E_; i += 128) sh[i] = g_h[b * N_ * E_ + i];
    if (tid < E_) sq[tid] = g_q[b * E_ + tid];
    __syncthreads();
    if (tid < N_) {
        float acc = 0.f;
        for (int e = 0; e < E_; e++) acc += sh[tid * E_ + e] * sq[e];
        sl[tid] = acc;
    }
    __syncthreads();
    if (tid == 0) {
        float m = sl[0];
        for (int n = 1; n < N_; n++) m = fmaxf(m, sl[n]);
        float s = 0.f;
        for (int n = 0; n < N_; n++) { float ev = expf(sl[n] - m); sp[n] = ev; s += ev; }
        float inv = 1.f / s;
        for (int n = 0; n < N_; n++) sp[n] *= inv;
    }
    __syncthreads();
    if (tid < E_) {
        float u = 0.f;
        for (int n = 0; n < N_; n++) u += sp[n] * sh[n * E_ + tid];
        su[tid] = u;
    }
    __syncthreads();
    if (tid < E_) {
        int f_ = tid;
        float acc = sq[f_] + H_b[f_];
        for (int e = 0; e < E_; e++) acc += su[e] * H_w[f_ * E_ + e];
        float ao = *a_out_p;
        g_ya[b * E_ + f_] = (acc >= 0.f) ? acc : ao * acc;
    }
}

// ============================================================
// K4: out[b][v] = ya[b] . R_w[v] + R_b[v]  (512 x 32000, K=100)
//     128x64 tiles, FFMA2.
// ============================================================
#define NP 50
#define K4_SMEM_FLOATS (128*NP*2 + 64*NP*2)
__global__ __launch_bounds__(256) void out_kernel(const float* __restrict__ R_w,
                                                  const float* __restrict__ R_b,
                                                  float* __restrict__ out) {
    extern __shared__ float osm[];
    float* sA2 = osm;                 // [p][bi] pairs, 128 rows
    float* sB2 = osm + 128 * NP * 2;  // [p][vi] pairs, 64 cols
    int tid = threadIdx.x;
    int v0 = blockIdx.x * 64, b0 = blockIdx.y * 128;
    for (int i = tid; i < 128 * NP; i += 256) {
        int bi = i / NP, p = i % NP;
        float2 v = *(const float2*)(g_ya + (long)(b0 + bi) * E_ + 2 * p);
        sA2[(p * 128 + bi) * 2]     = v.x;
        sA2[(p * 128 + bi) * 2 + 1] = v.y;
    }
    for (int i = tid; i < 64 * NP; i += 256) {
        int vi = i / NP, p = i % NP;
        float2 v = *(const float2*)(R_w + (long)(v0 + vi) * E_ + 2 * p);
        sB2[(p * 64 + vi) * 2]     = v.x;
        sB2[(p * 64 + vi) * 2 + 1] = v.y;
    }
    __syncthreads();
    int bi8 = (tid >> 4) << 3;    // rows bi8..bi8+7
    int vj  = tid & 15;           // cols {vj, vj+16, vj+32, vj+48}
    unsigned long long acc2[8][4];
#pragma unroll
    for (int k = 0; k < 8; k++)
#pragma unroll
        for (int j = 0; j < 4; j++) acc2[k][j] = 0ull;
#pragma unroll 2
    for (int p = 0; p < NP; p++) {
        unsigned long long a2[8], b2[4];
#pragma unroll
        for (int j = 0; j < 4; j++) b2[j] = lds2(sB2 + (p * 64 + vj + 16 * j) * 2);
#pragma unroll
        for (int k = 0; k < 8; k++) a2[k] = lds2(sA2 + (p * 128 + bi8 + k) * 2);
#pragma unroll
        for (int k = 0; k < 8; k++)
#pragma unroll
            for (int j = 0; j < 4; j++) ffma2(acc2[k][j], a2[k], b2[j]);
    }
    float rb[4];
#pragma unroll
    for (int j = 0; j < 4; j++) rb[j] = R_b[v0 + vj + 16 * j];
#pragma unroll
    for (int k = 0; k < 8; k++) {
#pragma unroll
        for (int j = 0; j < 4; j++) {
            out[(long)(b0 + bi8 + k) * V_ + v0 + vj + 16 * j] = hadd2(acc2[k][j]) + rb[j];
        }
    }
}

// ============================================================
extern "C" void kernel_launch(void* const* d_in, const int* in_sizes, int n_in,
                              void* d_out, int out_size) {
    const float* in_data = (const float*)d_in[0];
    const float* f       = (const float*)d_in[1];
    const float* h0      = (const float*)d_in[2];
    const float* w_mem   = (const float*)d_in[3];
    const float* U_w     = (const float*)d_in[4];
    const float* V_w     = (const float*)d_in[5];
    const float* W_w     = (const float*)d_in[6];
    const float* a_dm    = (const float*)d_in[7];
    const float* H_w     = (const float*)d_in[8];
    const float* H_b     = (const float*)d_in[9];
    const float* R_w     = (const float*)d_in[10];
    const float* R_b     = (const float*)d_in[11];
    const float* a_out   = (const float*)d_in[12];
    float* out = (float*)d_out;

    cudaFuncSetAttribute(scan_mma_kernel, cudaFuncAttributeMaxDynamicSharedMemorySize,
                         SCAN_SMEM);
    const int k4_smem = K4_SMEM_FLOATS * (int)sizeof(float);
    cudaFuncSetAttribute(out_kernel, cudaFuncAttributeMaxDynamicSharedMemorySize,
                         k4_smem);

    infos_kernel<<<(B_ * NCH * E_ + 255) / 256, 256>>>(in_data, f);
    q_kernel<<<B_, 128>>>(in_data, f);
    scan_mma_kernel<<<B_ / NB, NTH, SCAN_SMEM>>>(U_w, V_w, W_w, w_mem, h0, a_dm);
    attn_kernel<<<B_, 128>>>(H_w, H_b, a_out);
    dim3 g4(V_ / 64, B_ / 128);
    out_kernel<<<g4, 256, k4_smem>>>(R_w, R_b, out);
}